// round 6
// baseline (speedup 1.0000x reference)
#include <cuda_runtime.h>
#include <math.h>

#define NN 6144
#define NDRUG 3072

// ---------- scratch (device globals; no allocation allowed) ----------
__device__ __align__(16) float g_norm[NN];
__device__ __align__(16) float g_xn[NN * 64];       // node_f * col_norm
__device__ __align__(16) float g_target[NN * 64];   // atomic accum
__device__ __align__(16) float g_aux[NN * 64];
__device__ __align__(16) float g_q[4 * NN * 16];    // head-major
__device__ __align__(16) float g_k[4 * NN * 16];
__device__ __align__(16) float g_v[4 * NN * 16];
__device__ __align__(16) float g_oacc[NN * 64];     // attention numerator (atomic)
__device__ __align__(16) float g_lacc[NN * 4];      // softmax denominators (atomic)

// ===== K1: degree norms + zero atomic accumulators. grid 768, block 256 =====
__global__ __launch_bounds__(256) void k_deg(const float* __restrict__ graph) {
    int wid = threadIdx.x >> 5, lane = threadIdx.x & 31;
    int row = blockIdx.x * 8 + wid;
    const float4* gr = reinterpret_cast<const float4*>(graph + (size_t)row * NN);
    float s = 0.f;
    #pragma unroll 4
    for (int i = lane; i < NN / 4; i += 32) { float4 t = gr[i]; s += (t.x + t.y) + (t.z + t.w); }
    #pragma unroll
    for (int o = 16; o; o >>= 1) s += __shfl_xor_sync(0xffffffffu, s, o);
    if (lane == 0) g_norm[row] = rsqrtf(fmaxf(s, 1.0f));
    int t = blockIdx.x * 256 + threadIdx.x;             // 196608 threads total
    g_target[t] = 0.f; g_target[t + 196608] = 0.f;
    g_oacc[t] = 0.f;   g_oacc[t + 196608] = 0.f;
    if (t < NN * 4) g_lacc[t] = 0.f;
}

// ===== K2: per-type projection scaled by column norm. grid 1536, block 256 =====
__global__ __launch_bounds__(256) void k_proj(const float* __restrict__ drug_f,
                                              const float* __restrict__ dis_f,
                                              const float* __restrict__ drug_w,
                                              const float* __restrict__ dis_w) {
    __shared__ float w[4096];
    __shared__ float fr[256];
    int row0 = blockIdx.x * 4;
    const float* W = (row0 < NDRUG) ? drug_w : dis_w;
    for (int i = threadIdx.x; i < 4096; i += 256) w[i] = W[i];
    int r = threadIdx.x >> 6, d = threadIdx.x & 63;
    int row = row0 + r;
    fr[r * 64 + d] = (row0 < NDRUG) ? drug_f[(size_t)row * 64 + d]
                                    : dis_f[(size_t)(row - NDRUG) * 64 + d];
    __syncthreads();
    float acc = 0.f;
    #pragma unroll 16
    for (int k = 0; k < 64; k++) acc += fr[r * 64 + k] * w[k * 64 + d];
    g_xn[(size_t)row * 64 + d] = acc * g_norm[row];
}

// ===== K3: target += (graph @ xn) * row_norm. grid (96,3), block 256 =====
__global__ __launch_bounds__(256) void k_spmm(const float* __restrict__ graph) {
    __shared__ float As[64 * 33];
    __shared__ float Bs[32 * 72];
    int tx = threadIdx.x & 15, ty = threadIdx.x >> 4;
    int rowbase = blockIdx.x * 64;
    int kstart = blockIdx.y * 2048, kend = kstart + 2048;
    float acc[4][4];
    #pragma unroll
    for (int i = 0; i < 4; i++)
        #pragma unroll
        for (int j = 0; j < 4; j++) acc[i][j] = 0.f;
    int alr = threadIdx.x >> 2, alk = (threadIdx.x & 3) * 8;
    int bbk = threadIdx.x >> 3, bbc = (threadIdx.x & 7) * 8;
    for (int kb = kstart; kb < kend; kb += 32) {
        float4 a0 = *reinterpret_cast<const float4*>(graph + (size_t)(rowbase + alr) * NN + kb + alk);
        float4 a1 = *reinterpret_cast<const float4*>(graph + (size_t)(rowbase + alr) * NN + kb + alk + 4);
        float4 b0 = *reinterpret_cast<const float4*>(g_xn + (size_t)(kb + bbk) * 64 + bbc);
        float4 b1 = *reinterpret_cast<const float4*>(g_xn + (size_t)(kb + bbk) * 64 + bbc + 4);
        As[alr * 33 + alk + 0] = a0.x; As[alr * 33 + alk + 1] = a0.y;
        As[alr * 33 + alk + 2] = a0.z; As[alr * 33 + alk + 3] = a0.w;
        As[alr * 33 + alk + 4] = a1.x; As[alr * 33 + alk + 5] = a1.y;
        As[alr * 33 + alk + 6] = a1.z; As[alr * 33 + alk + 7] = a1.w;
        *reinterpret_cast<float4*>(Bs + bbk * 72 + bbc)     = b0;
        *reinterpret_cast<float4*>(Bs + bbk * 72 + bbc + 4) = b1;
        __syncthreads();
        #pragma unroll 8
        for (int kk = 0; kk < 32; kk++) {
            float a_0 = As[ty * 33 + kk];
            float a_1 = As[(ty + 16) * 33 + kk];
            float a_2 = As[(ty + 32) * 33 + kk];
            float a_3 = As[(ty + 48) * 33 + kk];
            float4 b = *reinterpret_cast<const float4*>(Bs + kk * 72 + tx * 4);
            acc[0][0] += a_0 * b.x; acc[0][1] += a_0 * b.y; acc[0][2] += a_0 * b.z; acc[0][3] += a_0 * b.w;
            acc[1][0] += a_1 * b.x; acc[1][1] += a_1 * b.y; acc[1][2] += a_1 * b.z; acc[1][3] += a_1 * b.w;
            acc[2][0] += a_2 * b.x; acc[2][1] += a_2 * b.y; acc[2][2] += a_2 * b.z; acc[2][3] += a_2 * b.w;
            acc[3][0] += a_3 * b.x; acc[3][1] += a_3 * b.y; acc[3][2] += a_3 * b.z; acc[3][3] += a_3 * b.w;
        }
        __syncthreads();
    }
    #pragma unroll
    for (int i = 0; i < 4; i++) {
        int row = rowbase + ty + 16 * i;
        float nr = g_norm[row];
        #pragma unroll
        for (int j = 0; j < 4; j++)
            atomicAdd(&g_target[(size_t)row * 64 + tx * 4 + j], acc[i][j] * nr);
    }
}

// ===== K4: time embedding + denoise MLP -> aux. grid 192, block 256 =====
__global__ __launch_bounds__(256) void k_mlp(const int* __restrict__ tsteps,
                                             const float* __restrict__ emb_w, const float* __restrict__ emb_b,
                                             const float* __restrict__ in_w,  const float* __restrict__ in_b,
                                             const float* __restrict__ out_w, const float* __restrict__ out_b) {
    __shared__ float cs[32 * 81];   // per-node [target(64) | emb(16)]
    __shared__ float hs[32 * 257];  // hidden 256
    int tid = threadIdx.x;
    int base = blockIdx.x * 32;
    for (int idx = tid; idx < 32 * 64; idx += 256) {
        int n = idx >> 6, d = idx & 63;
        cs[n * 81 + d] = g_target[(size_t)(base + n) * 64 + d];
    }
    __syncthreads();
    for (int idx = tid; idx < 512; idx += 256) {
        int n = idx >> 4, e = idx & 15;
        float t = (float)tsteps[base + n];
        float acc = emb_b[e];
        for (int k = 0; k < 16; k++) {
            int j = k & 7;
            float fr = expf(-1.15129254649702f * (float)j);
            float te = (k < 8) ? cosf(t * fr) : sinf(t * fr);
            acc += te * emb_w[k * 16 + e];
        }
        cs[n * 81 + 64 + e] = acc;
    }
    __syncthreads();
    {   // hidden unit j = tid for all 32 nodes
        float bj = in_b[tid];
        for (int n = 0; n < 32; n++) {
            float acc = bj;
            #pragma unroll 16
            for (int k = 0; k < 80; k++) acc += cs[n * 81 + k] * in_w[k * 256 + tid];
            hs[n * 257 + tid] = tanhf(acc);
        }
    }
    __syncthreads();
    for (int rep = 0; rep < 8; rep++) {
        int idx = tid + rep * 256;
        int n = idx >> 6, d = idx & 63;
        float acc = out_b[d];
        #pragma unroll 16
        for (int k = 0; k < 256; k++) acc += hs[n * 257 + k] * out_w[k * 64 + d];
        g_aux[(size_t)(base + n) * 64 + d] = acc;
    }
}

// ===== K5: q/k/v projections (head-major). grid 1536, block 256 =====
__global__ __launch_bounds__(256) void k_qkv(const float* __restrict__ wq, const float* __restrict__ bq,
                                             const float* __restrict__ wk, const float* __restrict__ bk,
                                             const float* __restrict__ wv, const float* __restrict__ bv) {
    __shared__ float w[4096];
    __shared__ float st[256], sa[256];
    int r = threadIdx.x >> 6, d = threadIdx.x & 63;
    int row = blockIdx.x * 4 + r;
    st[r * 64 + d] = g_target[(size_t)row * 64 + d];
    sa[r * 64 + d] = g_aux[(size_t)row * 64 + d];
    int h = d >> 4, hd = d & 15;
    size_t oidx = ((size_t)h * NN + row) * 16 + hd;

    for (int i = threadIdx.x; i < 4096; i += 256) w[i] = wq[i];
    __syncthreads();
    float acc = bq[d];
    #pragma unroll 16
    for (int k = 0; k < 64; k++) acc += st[r * 64 + k] * w[k * 64 + d];
    g_q[oidx] = acc;
    __syncthreads();

    for (int i = threadIdx.x; i < 4096; i += 256) w[i] = wk[i];
    __syncthreads();
    acc = bk[d];
    #pragma unroll 16
    for (int k = 0; k < 64; k++) acc += sa[r * 64 + k] * w[k * 64 + d];
    g_k[oidx] = acc;
    __syncthreads();

    for (int i = threadIdx.x; i < 4096; i += 256) w[i] = wv[i];
    __syncthreads();
    acc = bv[d];
    #pragma unroll 16
    for (int k = 0; k < 64; k++) acc += sa[r * 64 + k] * w[k * 64 + d];
    g_v[oidx] = acc;
}

// ===== K6: attention (unnormalized exp, split keys). grid (48,4,3), block 128 =====
__global__ __launch_bounds__(128) void k_attn() {
    __shared__ float4 Ks[128 * 4];
    __shared__ float4 Vs[128 * 4];
    int h = blockIdx.y;
    int qn = blockIdx.x * 128 + threadIdx.x;
    const float4* qp = reinterpret_cast<const float4*>(g_q + ((size_t)h * NN + qn) * 16);
    float4 q0 = qp[0], q1 = qp[1], q2 = qp[2], q3 = qp[3];
    float4 o0 = {0,0,0,0}, o1 = {0,0,0,0}, o2 = {0,0,0,0}, o3 = {0,0,0,0};
    float l = 0.f;
    int kbase = blockIdx.z * 2048;
    for (int c0 = 0; c0 < 2048; c0 += 128) {
        int key = kbase + c0 + threadIdx.x;
        const float4* kp = reinterpret_cast<const float4*>(g_k + ((size_t)h * NN + key) * 16);
        const float4* vp = reinterpret_cast<const float4*>(g_v + ((size_t)h * NN + key) * 16);
        float4 kr0 = kp[0], kr1 = kp[1], kr2 = kp[2], kr3 = kp[3];
        float4 vr0 = vp[0], vr1 = vp[1], vr2 = vp[2], vr3 = vp[3];
        __syncthreads();
        Ks[threadIdx.x * 4 + 0] = kr0; Ks[threadIdx.x * 4 + 1] = kr1;
        Ks[threadIdx.x * 4 + 2] = kr2; Ks[threadIdx.x * 4 + 3] = kr3;
        Vs[threadIdx.x * 4 + 0] = vr0; Vs[threadIdx.x * 4 + 1] = vr1;
        Vs[threadIdx.x * 4 + 2] = vr2; Vs[threadIdx.x * 4 + 3] = vr3;
        __syncthreads();
        #pragma unroll 4
        for (int kk = 0; kk < 128; kk++) {
            float4 k0 = Ks[kk * 4], k1 = Ks[kk * 4 + 1], k2 = Ks[kk * 4 + 2], k3 = Ks[kk * 4 + 3];
            float s = q0.x * k0.x + q0.y * k0.y + q0.z * k0.z + q0.w * k0.w
                    + q1.x * k1.x + q1.y * k1.y + q1.z * k1.z + q1.w * k1.w
                    + q2.x * k2.x + q2.y * k2.y + q2.z * k2.z + q2.w * k2.w
                    + q3.x * k3.x + q3.y * k3.y + q3.z * k3.z + q3.w * k3.w;
            float p = __expf(s * 0.25f);
            l += p;
            float4 v0 = Vs[kk * 4], v1 = Vs[kk * 4 + 1], v2 = Vs[kk * 4 + 2], v3 = Vs[kk * 4 + 3];
            o0.x += p * v0.x; o0.y += p * v0.y; o0.z += p * v0.z; o0.w += p * v0.w;
            o1.x += p * v1.x; o1.y += p * v1.y; o1.z += p * v1.z; o1.w += p * v1.w;
            o2.x += p * v2.x; o2.y += p * v2.y; o2.z += p * v2.z; o2.w += p * v2.w;
            o3.x += p * v3.x; o3.y += p * v3.y; o3.z += p * v3.z; o3.w += p * v3.w;
        }
    }
    float* op = g_oacc + (size_t)qn * 64 + h * 16;
    atomicAdd(op + 0,  o0.x); atomicAdd(op + 1,  o0.y); atomicAdd(op + 2,  o0.z); atomicAdd(op + 3,  o0.w);
    atomicAdd(op + 4,  o1.x); atomicAdd(op + 5,  o1.y); atomicAdd(op + 6,  o1.z); atomicAdd(op + 7,  o1.w);
    atomicAdd(op + 8,  o2.x); atomicAdd(op + 9,  o2.y); atomicAdd(op + 10, o2.z); atomicAdd(op + 11, o2.w);
    atomicAdd(op + 12, o3.x); atomicAdd(op + 13, o3.y); atomicAdd(op + 14, o3.z); atomicAdd(op + 15, o3.w);
    atomicAdd(&g_lacc[qn * 4 + h], l);
}

// ===== K7: wo proj + fuse + residual LN -> out. grid 1536, block 256 =====
__global__ __launch_bounds__(256) void k_final(const float* __restrict__ wo, const float* __restrict__ bo,
                                               const float* __restrict__ fuse_w, const float* __restrict__ fuse_b,
                                               const float* __restrict__ ln_g, const float* __restrict__ ln_b,
                                               float* __restrict__ out) {
    __shared__ float w[4096];
    __shared__ float st[256], sao[256], sy[256];
    int r = threadIdx.x >> 6, d = threadIdx.x & 63;
    int row = blockIdx.x * 4 + r;
    st[r * 64 + d] = g_target[(size_t)row * 64 + d];
    float lh = g_lacc[row * 4 + (d >> 4)];
    sy[r * 64 + d] = g_oacc[(size_t)row * 64 + d] / lh;   // normalized attn (pre-wo)
    for (int i = threadIdx.x; i < 4096; i += 256) w[i] = wo[i];
    __syncthreads();
    float acc = bo[d];
    #pragma unroll 16
    for (int k = 0; k < 64; k++) acc += sy[r * 64 + k] * w[k * 64 + d];
    __syncthreads();
    sao[r * 64 + d] = acc;                                 // attn_out
    for (int i = threadIdx.x; i < 4096; i += 256) w[i] = fuse_w[i];          // rows 0..63
    __syncthreads();
    float f = fuse_b[d];
    #pragma unroll 16
    for (int k = 0; k < 64; k++) f += st[r * 64 + k] * w[k * 64 + d];
    __syncthreads();
    for (int i = threadIdx.x; i < 4096; i += 256) w[i] = fuse_w[4096 + i];   // rows 64..127
    __syncthreads();
    #pragma unroll 16
    for (int k = 0; k < 64; k++) f += sao[r * 64 + k] * w[k * 64 + d];
    float y = f + st[r * 64 + d];                          // residual
    __syncthreads();
    sy[r * 64 + d] = y;
    __syncthreads();
    float mu = 0.f;
    #pragma unroll 16
    for (int k = 0; k < 64; k++) mu += sy[r * 64 + k];
    mu *= (1.0f / 64.0f);
    float var = 0.f;
    #pragma unroll 16
    for (int k = 0; k < 64; k++) { float t = sy[r * 64 + k] - mu; var += t * t; }
    var *= (1.0f / 64.0f);
    out[(size_t)row * 64 + d] = (y - mu) * rsqrtf(var + 1e-5f) * ln_g[d] + ln_b[d];
}

extern "C" void kernel_launch(void* const* d_in, const int* in_sizes, int n_in,
                              void* d_out, int out_size) {
    const float* graph     = (const float*)d_in[0];
    const float* drug_f    = (const float*)d_in[1];
    const float* disease_f = (const float*)d_in[2];
    const int*   tsteps    = (const int*)  d_in[3];
    const float* drug_w    = (const float*)d_in[4];
    const float* disease_w = (const float*)d_in[5];
    const float* emb_w     = (const float*)d_in[6];
    const float* emb_b     = (const float*)d_in[7];
    const float* in_w      = (const float*)d_in[8];
    const float* in_b      = (const float*)d_in[9];
    const float* out_w     = (const float*)d_in[10];
    const float* out_b     = (const float*)d_in[11];
    const float* wq = (const float*)d_in[12]; const float* bq = (const float*)d_in[13];
    const float* wk = (const float*)d_in[14]; const float* bk = (const float*)d_in[15];
    const float* wv = (const float*)d_in[16]; const float* bv = (const float*)d_in[17];
    const float* wo = (const float*)d_in[18]; const float* bo = (const float*)d_in[19];
    const float* fuse_w = (const float*)d_in[20]; const float* fuse_b = (const float*)d_in[21];
    const float* ln_g   = (const float*)d_in[22]; const float* ln_b   = (const float*)d_in[23];
    float* out = (float*)d_out;

    k_deg  <<<768, 256>>>(graph);
    k_proj <<<1536, 256>>>(drug_f, disease_f, drug_w, disease_w);
    k_spmm <<<dim3(96, 3), 256>>>(graph);
    k_mlp  <<<192, 256>>>(tsteps, emb_w, emb_b, in_w, in_b, out_w, out_b);
    k_qkv  <<<1536, 256>>>(wq, bq, wk, bk, wv, bv);
    k_attn <<<dim3(48, 4, 3), 128>>>();
    k_final<<<1536, 256>>>(wo, bo, fuse_w, fuse_b, ln_g, ln_b, out);
}

// round 7
// speedup vs baseline: 1.0873x; 1.0873x over previous
#include <cuda_runtime.h>
#include <math.h>

#define NN 6144
#define NDRUG 3072

// ---------- packed f32x2 helpers ----------
__device__ __forceinline__ unsigned long long pack2(float lo, float hi) {
    unsigned long long r; asm("mov.b64 %0, {%1, %2};" : "=l"(r) : "f"(lo), "f"(hi)); return r;
}
__device__ __forceinline__ void unpack2(unsigned long long v, float& lo, float& hi) {
    asm("mov.b64 {%0, %1}, %2;" : "=f"(lo), "=f"(hi) : "l"(v));
}
__device__ __forceinline__ void fma2(unsigned long long& d, unsigned long long a, unsigned long long b) {
    asm("fma.rn.f32x2 %0, %1, %2, %0;" : "+l"(d) : "l"(a), "l"(b));
}

// ---------- scratch (device globals; no allocation allowed) ----------
__device__ __align__(16) float g_norm[NN];
__device__ __align__(16) float g_xn[NN * 64];       // node_f * col_norm
__device__ __align__(16) float g_target[NN * 64];   // atomic accum
__device__ __align__(16) float g_aux[NN * 64];
__device__ __align__(16) float g_q[4 * NN * 16];    // head-major
__device__ __align__(16) float g_k[4 * NN * 16];
__device__ __align__(16) float g_v[4 * NN * 16];
__device__ __align__(16) float g_oacc[NN * 64];     // attention numerator (atomic)
__device__ __align__(16) float g_lacc[NN * 4];      // softmax denominators (atomic)

// ===== K1: degree norms + zero atomic accumulators. grid 768, block 256 =====
__global__ __launch_bounds__(256) void k_deg(const float* __restrict__ graph) {
    int wid = threadIdx.x >> 5, lane = threadIdx.x & 31;
    int row = blockIdx.x * 8 + wid;
    const float4* gr = reinterpret_cast<const float4*>(graph + (size_t)row * NN);
    float s = 0.f;
    #pragma unroll 4
    for (int i = lane; i < NN / 4; i += 32) { float4 t = gr[i]; s += (t.x + t.y) + (t.z + t.w); }
    #pragma unroll
    for (int o = 16; o; o >>= 1) s += __shfl_xor_sync(0xffffffffu, s, o);
    if (lane == 0) g_norm[row] = rsqrtf(fmaxf(s, 1.0f));
    int t = blockIdx.x * 256 + threadIdx.x;             // 196608 threads total
    g_target[t] = 0.f; g_target[t + 196608] = 0.f;
    g_oacc[t] = 0.f;   g_oacc[t + 196608] = 0.f;
    if (t < NN * 4) g_lacc[t] = 0.f;
}

// ===== K2: per-type projection scaled by column norm. grid 1536, block 256 =====
__global__ __launch_bounds__(256) void k_proj(const float* __restrict__ drug_f,
                                              const float* __restrict__ dis_f,
                                              const float* __restrict__ drug_w,
                                              const float* __restrict__ dis_w) {
    __shared__ float w[4096];
    __shared__ float fr[256];
    int row0 = blockIdx.x * 4;
    const float* W = (row0 < NDRUG) ? drug_w : dis_w;
    for (int i = threadIdx.x; i < 4096; i += 256) w[i] = W[i];
    int r = threadIdx.x >> 6, d = threadIdx.x & 63;
    int row = row0 + r;
    fr[r * 64 + d] = (row0 < NDRUG) ? drug_f[(size_t)row * 64 + d]
                                    : dis_f[(size_t)(row - NDRUG) * 64 + d];
    __syncthreads();
    float acc = 0.f;
    #pragma unroll 16
    for (int k = 0; k < 64; k++) acc += fr[r * 64 + k] * w[k * 64 + d];
    g_xn[(size_t)row * 64 + d] = acc * g_norm[row];
}

// ===== K3: target += (graph @ xn) * row_norm. grid (96,3), block 256, f32x2 =====
__global__ __launch_bounds__(256) void k_spmm(const float* __restrict__ graph) {
    __shared__ __align__(16) float As[64 * 33];
    __shared__ __align__(16) float Bs[32 * 72];
    int tx = threadIdx.x & 15, ty = threadIdx.x >> 4;
    int rowbase = blockIdx.x * 64;
    int kstart = blockIdx.y * 2048, kend = kstart + 2048;
    unsigned long long acc2[4][2];
    #pragma unroll
    for (int i = 0; i < 4; i++) { acc2[i][0] = 0ull; acc2[i][1] = 0ull; }
    int alr = threadIdx.x >> 2, alk = (threadIdx.x & 3) * 8;
    int bbk = threadIdx.x >> 3, bbc = (threadIdx.x & 7) * 8;
    for (int kb = kstart; kb < kend; kb += 32) {
        float4 a0 = *reinterpret_cast<const float4*>(graph + (size_t)(rowbase + alr) * NN + kb + alk);
        float4 a1 = *reinterpret_cast<const float4*>(graph + (size_t)(rowbase + alr) * NN + kb + alk + 4);
        float4 b0 = *reinterpret_cast<const float4*>(g_xn + (size_t)(kb + bbk) * 64 + bbc);
        float4 b1 = *reinterpret_cast<const float4*>(g_xn + (size_t)(kb + bbk) * 64 + bbc + 4);
        As[alr * 33 + alk + 0] = a0.x; As[alr * 33 + alk + 1] = a0.y;
        As[alr * 33 + alk + 2] = a0.z; As[alr * 33 + alk + 3] = a0.w;
        As[alr * 33 + alk + 4] = a1.x; As[alr * 33 + alk + 5] = a1.y;
        As[alr * 33 + alk + 6] = a1.z; As[alr * 33 + alk + 7] = a1.w;
        *reinterpret_cast<float4*>(Bs + bbk * 72 + bbc)     = b0;
        *reinterpret_cast<float4*>(Bs + bbk * 72 + bbc + 4) = b1;
        __syncthreads();
        #pragma unroll 8
        for (int kk = 0; kk < 32; kk++) {
            float a_0 = As[ty * 33 + kk];
            float a_1 = As[(ty + 16) * 33 + kk];
            float a_2 = As[(ty + 32) * 33 + kk];
            float a_3 = As[(ty + 48) * 33 + kk];
            ulonglong2 b2 = *reinterpret_cast<const ulonglong2*>(Bs + kk * 72 + tx * 4);
            unsigned long long ap;
            ap = pack2(a_0, a_0); fma2(acc2[0][0], ap, b2.x); fma2(acc2[0][1], ap, b2.y);
            ap = pack2(a_1, a_1); fma2(acc2[1][0], ap, b2.x); fma2(acc2[1][1], ap, b2.y);
            ap = pack2(a_2, a_2); fma2(acc2[2][0], ap, b2.x); fma2(acc2[2][1], ap, b2.y);
            ap = pack2(a_3, a_3); fma2(acc2[3][0], ap, b2.x); fma2(acc2[3][1], ap, b2.y);
        }
        __syncthreads();
    }
    #pragma unroll
    for (int i = 0; i < 4; i++) {
        int row = rowbase + ty + 16 * i;
        float nr = g_norm[row];
        float c0, c1, c2, c3;
        unpack2(acc2[i][0], c0, c1);
        unpack2(acc2[i][1], c2, c3);
        float* tp = &g_target[(size_t)row * 64 + tx * 4];
        atomicAdd(tp + 0, c0 * nr); atomicAdd(tp + 1, c1 * nr);
        atomicAdd(tp + 2, c2 * nr); atomicAdd(tp + 3, c3 * nr);
    }
}

// ===== K4: time embedding + denoise MLP -> aux. grid 192, block 256 (loop-swapped) =====
__global__ __launch_bounds__(256) void k_mlp(const int* __restrict__ tsteps,
                                             const float* __restrict__ emb_w, const float* __restrict__ emb_b,
                                             const float* __restrict__ in_w,  const float* __restrict__ in_b,
                                             const float* __restrict__ out_w, const float* __restrict__ out_b) {
    __shared__ float cs[32 * 81];   // per-node [target(64) | emb(16)]
    __shared__ float hs[32 * 257];  // hidden 256
    int tid = threadIdx.x;
    int base = blockIdx.x * 32;
    for (int idx = tid; idx < 32 * 64; idx += 256) {
        int n = idx >> 6, d = idx & 63;
        cs[n * 81 + d] = g_target[(size_t)(base + n) * 64 + d];
    }
    for (int idx = tid; idx < 512; idx += 256) {
        int n = idx >> 4, e = idx & 15;
        float t = (float)tsteps[base + n];
        float acc = emb_b[e];
        for (int k = 0; k < 16; k++) {
            int j = k & 7;
            float fr = expf(-1.15129254649702f * (float)j);
            float te = (k < 8) ? cosf(t * fr) : sinf(t * fr);
            acc += te * emb_w[k * 16 + e];
        }
        cs[n * 81 + 64 + e] = acc;
    }
    __syncthreads();
    {   // hidden unit j = tid for all 32 nodes; 1 LDG per 32 FMAs
        float acc[32];
        #pragma unroll
        for (int n = 0; n < 32; n++) acc[n] = 0.f;
        for (int k = 0; k < 80; k++) {
            float w = in_w[k * 256 + tid];
            #pragma unroll
            for (int n = 0; n < 32; n++) acc[n] += cs[n * 81 + k] * w;
        }
        float bj = in_b[tid];
        #pragma unroll
        for (int n = 0; n < 32; n++) hs[n * 257 + tid] = tanhf(acc[n] + bj);
    }
    __syncthreads();
    {   // output: thread owns column d for 8 nodes; 1 LDG per 8 FMAs
        int d = tid & 63, g = tid >> 6;
        float oa[8];
        #pragma unroll
        for (int nn = 0; nn < 8; nn++) oa[nn] = 0.f;
        for (int k = 0; k < 256; k++) {
            float w = out_w[k * 64 + d];
            #pragma unroll
            for (int nn = 0; nn < 8; nn++) oa[nn] += hs[(g * 8 + nn) * 257 + k] * w;
        }
        float bd = out_b[d];
        #pragma unroll
        for (int nn = 0; nn < 8; nn++)
            g_aux[(size_t)(base + g * 8 + nn) * 64 + d] = oa[nn] + bd;
    }
}

// ===== K5: q/k/v projections (head-major). grid 1536, block 256 =====
__global__ __launch_bounds__(256) void k_qkv(const float* __restrict__ wq, const float* __restrict__ bq,
                                             const float* __restrict__ wk, const float* __restrict__ bk,
                                             const float* __restrict__ wv, const float* __restrict__ bv) {
    __shared__ float w[4096];
    __shared__ float st[256], sa[256];
    int r = threadIdx.x >> 6, d = threadIdx.x & 63;
    int row = blockIdx.x * 4 + r;
    st[r * 64 + d] = g_target[(size_t)row * 64 + d];
    sa[r * 64 + d] = g_aux[(size_t)row * 64 + d];
    int h = d >> 4, hd = d & 15;
    size_t oidx = ((size_t)h * NN + row) * 16 + hd;

    for (int i = threadIdx.x; i < 4096; i += 256) w[i] = wq[i];
    __syncthreads();
    float acc = bq[d];
    #pragma unroll 16
    for (int k = 0; k < 64; k++) acc += st[r * 64 + k] * w[k * 64 + d];
    g_q[oidx] = acc;
    __syncthreads();

    for (int i = threadIdx.x; i < 4096; i += 256) w[i] = wk[i];
    __syncthreads();
    acc = bk[d];
    #pragma unroll 16
    for (int k = 0; k < 64; k++) acc += sa[r * 64 + k] * w[k * 64 + d];
    g_k[oidx] = acc;
    __syncthreads();

    for (int i = threadIdx.x; i < 4096; i += 256) w[i] = wv[i];
    __syncthreads();
    acc = bv[d];
    #pragma unroll 16
    for (int k = 0; k < 64; k++) acc += sa[r * 64 + k] * w[k * 64 + d];
    g_v[oidx] = acc;
}

// ===== K6: attention (unnormalized exp, split keys), f32x2. grid (48,4,3), block 128 =====
__global__ __launch_bounds__(128) void k_attn() {
    __shared__ __align__(16) ulonglong2 Ks[128 * 4];   // 64B per key
    __shared__ __align__(16) ulonglong2 Vs[128 * 4];
    int h = blockIdx.y;
    int qn = blockIdx.x * 128 + threadIdx.x;
    const unsigned long long* qp = reinterpret_cast<const unsigned long long*>(g_q + ((size_t)h * NN + qn) * 16);
    unsigned long long q2[8];
    #pragma unroll
    for (int i = 0; i < 8; i++) q2[i] = qp[i];
    unsigned long long o2[8];
    #pragma unroll
    for (int i = 0; i < 8; i++) o2[i] = 0ull;
    float l = 0.f;
    int kbase = blockIdx.z * 2048;
    for (int c0 = 0; c0 < 2048; c0 += 128) {
        int key = kbase + c0 + threadIdx.x;
        const ulonglong2* kp = reinterpret_cast<const ulonglong2*>(g_k + ((size_t)h * NN + key) * 16);
        const ulonglong2* vp = reinterpret_cast<const ulonglong2*>(g_v + ((size_t)h * NN + key) * 16);
        ulonglong2 kr0 = kp[0], kr1 = kp[1], kr2 = kp[2], kr3 = kp[3];
        ulonglong2 vr0 = vp[0], vr1 = vp[1], vr2 = vp[2], vr3 = vp[3];
        __syncthreads();
        Ks[threadIdx.x * 4 + 0] = kr0; Ks[threadIdx.x * 4 + 1] = kr1;
        Ks[threadIdx.x * 4 + 2] = kr2; Ks[threadIdx.x * 4 + 3] = kr3;
        Vs[threadIdx.x * 4 + 0] = vr0; Vs[threadIdx.x * 4 + 1] = vr1;
        Vs[threadIdx.x * 4 + 2] = vr2; Vs[threadIdx.x * 4 + 3] = vr3;
        __syncthreads();
        #pragma unroll 2
        for (int kk = 0; kk < 128; kk++) {
            unsigned long long s2 = 0ull;
            #pragma unroll
            for (int i = 0; i < 4; i++) {
                ulonglong2 kk2 = Ks[kk * 4 + i];
                fma2(s2, q2[2 * i], kk2.x);
                fma2(s2, q2[2 * i + 1], kk2.y);
            }
            float slo, shi; unpack2(s2, slo, shi);
            float p = __expf((slo + shi) * 0.25f);
            l += p;
            unsigned long long pp = pack2(p, p);
            #pragma unroll
            for (int i = 0; i < 4; i++) {
                ulonglong2 vv = Vs[kk * 4 + i];
                fma2(o2[2 * i], pp, vv.x);
                fma2(o2[2 * i + 1], pp, vv.y);
            }
        }
    }
    float* op = g_oacc + (size_t)qn * 64 + h * 16;
    #pragma unroll
    for (int i = 0; i < 8; i++) {
        float lo, hi; unpack2(o2[i], lo, hi);
        atomicAdd(op + 2 * i, lo);
        atomicAdd(op + 2 * i + 1, hi);
    }
    atomicAdd(&g_lacc[qn * 4 + h], l);
}

// ===== K7: wo proj + fuse + residual LN -> out. grid 1536, block 256 =====
__global__ __launch_bounds__(256) void k_final(const float* __restrict__ wo, const float* __restrict__ bo,
                                               const float* __restrict__ fuse_w, const float* __restrict__ fuse_b,
                                               const float* __restrict__ ln_g, const float* __restrict__ ln_b,
                                               float* __restrict__ out) {
    __shared__ float w[4096];
    __shared__ float st[256], sao[256], sy[256];
    int r = threadIdx.x >> 6, d = threadIdx.x & 63;
    int row = blockIdx.x * 4 + r;
    st[r * 64 + d] = g_target[(size_t)row * 64 + d];
    float lh = g_lacc[row * 4 + (d >> 4)];
    sy[r * 64 + d] = g_oacc[(size_t)row * 64 + d] / lh;   // normalized attn (pre-wo)
    for (int i = threadIdx.x; i < 4096; i += 256) w[i] = wo[i];
    __syncthreads();
    float acc = bo[d];
    #pragma unroll 16
    for (int k = 0; k < 64; k++) acc += sy[r * 64 + k] * w[k * 64 + d];
    __syncthreads();
    sao[r * 64 + d] = acc;                                 // attn_out
    for (int i = threadIdx.x; i < 4096; i += 256) w[i] = fuse_w[i];          // rows 0..63
    __syncthreads();
    float f = fuse_b[d];
    #pragma unroll 16
    for (int k = 0; k < 64; k++) f += st[r * 64 + k] * w[k * 64 + d];
    __syncthreads();
    for (int i = threadIdx.x; i < 4096; i += 256) w[i] = fuse_w[4096 + i];   // rows 64..127
    __syncthreads();
    #pragma unroll 16
    for (int k = 0; k < 64; k++) f += sao[r * 64 + k] * w[k * 64 + d];
    float y = f + st[r * 64 + d];                          // residual
    __syncthreads();
    sy[r * 64 + d] = y;
    __syncthreads();
    float mu = 0.f;
    #pragma unroll 16
    for (int k = 0; k < 64; k++) mu += sy[r * 64 + k];
    mu *= (1.0f / 64.0f);
    float var = 0.f;
    #pragma unroll 16
    for (int k = 0; k < 64; k++) { float t = sy[r * 64 + k] - mu; var += t * t; }
    var *= (1.0f / 64.0f);
    out[(size_t)row * 64 + d] = (y - mu) * rsqrtf(var + 1e-5f) * ln_g[d] + ln_b[d];
}

extern "C" void kernel_launch(void* const* d_in, const int* in_sizes, int n_in,
                              void* d_out, int out_size) {
    const float* graph     = (const float*)d_in[0];
    const float* drug_f    = (const float*)d_in[1];
    const float* disease_f = (const float*)d_in[2];
    const int*   tsteps    = (const int*)  d_in[3];
    const float* drug_w    = (const float*)d_in[4];
    const float* disease_w = (const float*)d_in[5];
    const float* emb_w     = (const float*)d_in[6];
    const float* emb_b     = (const float*)d_in[7];
    const float* in_w      = (const float*)d_in[8];
    const float* in_b      = (const float*)d_in[9];
    const float* out_w     = (const float*)d_in[10];
    const float* out_b     = (const float*)d_in[11];
    const float* wq = (const float*)d_in[12]; const float* bq = (const float*)d_in[13];
    const float* wk = (const float*)d_in[14]; const float* bk = (const float*)d_in[15];
    const float* wv = (const float*)d_in[16]; const float* bv = (const float*)d_in[17];
    const float* wo = (const float*)d_in[18]; const float* bo = (const float*)d_in[19];
    const float* fuse_w = (const float*)d_in[20]; const float* fuse_b = (const float*)d_in[21];
    const float* ln_g   = (const float*)d_in[22]; const float* ln_b   = (const float*)d_in[23];
    float* out = (float*)d_out;

    k_deg  <<<768, 256>>>(graph);
    k_proj <<<1536, 256>>>(drug_f, disease_f, drug_w, disease_w);
    k_spmm <<<dim3(96, 3), 256>>>(graph);
    k_mlp  <<<192, 256>>>(tsteps, emb_w, emb_b, in_w, in_b, out_w, out_b);
    k_qkv  <<<1536, 256>>>(wq, bq, wk, bk, wv, bv);
    k_attn <<<dim3(48, 4, 3), 128>>>();
    k_final<<<1536, 256>>>(wo, bo, fuse_w, fuse_b, ln_g, ln_b, out);
}

// round 8
// speedup vs baseline: 1.5694x; 1.4434x over previous
#include <cuda_runtime.h>
#include <math.h>

#define NN 6144
#define NDRUG 3072

// ---------- scratch (device globals; no allocation allowed) ----------
__device__ __align__(16) float g_norm[NN];
__device__ __align__(16) float g_xn[NN * 64];
__device__ __align__(16) float g_target[NN * 64];
__device__ __align__(16) float g_aux[NN * 64];
__device__ __align__(16) float g_q[4 * NN * 16];    // head-major
__device__ __align__(16) float g_k[4 * NN * 16];
__device__ __align__(16) float g_v[4 * NN * 16];
__device__ __align__(16) float g_oacc[NN * 64];
__device__ __align__(16) float g_lacc[NN * 4];

#define MMA_TF32(D, A, B0, B1) \
    asm volatile("mma.sync.aligned.m16n8k8.row.col.f32.tf32.tf32.f32 " \
                 "{%0,%1,%2,%3},{%4,%5,%6,%7},{%8,%9},{%0,%1,%2,%3};" \
                 : "+f"((D)[0]), "+f"((D)[1]), "+f"((D)[2]), "+f"((D)[3]) \
                 : "r"((A)[0]), "r"((A)[1]), "r"((A)[2]), "r"((A)[3]), "r"(B0), "r"(B1))

// ===== K1: degree norms + zero atomic accumulators. grid 768, block 256 =====
__global__ __launch_bounds__(256) void k_deg(const float* __restrict__ graph) {
    int wid = threadIdx.x >> 5, lane = threadIdx.x & 31;
    int row = blockIdx.x * 8 + wid;
    const float4* gr = reinterpret_cast<const float4*>(graph + (size_t)row * NN);
    float s = 0.f;
    #pragma unroll 4
    for (int i = lane; i < NN / 4; i += 32) { float4 t = gr[i]; s += (t.x + t.y) + (t.z + t.w); }
    #pragma unroll
    for (int o = 16; o; o >>= 1) s += __shfl_xor_sync(0xffffffffu, s, o);
    if (lane == 0) g_norm[row] = rsqrtf(fmaxf(s, 1.0f));
    int t = blockIdx.x * 256 + threadIdx.x;
    g_target[t] = 0.f; g_target[t + 196608] = 0.f;
    g_oacc[t] = 0.f;   g_oacc[t + 196608] = 0.f;
    if (t < NN * 4) g_lacc[t] = 0.f;
}

// ===== K2: per-type projection scaled by column norm. grid 1536, block 256 =====
__global__ __launch_bounds__(256) void k_proj(const float* __restrict__ drug_f,
                                              const float* __restrict__ dis_f,
                                              const float* __restrict__ drug_w,
                                              const float* __restrict__ dis_w) {
    __shared__ float w[4096];
    __shared__ float fr[256];
    int row0 = blockIdx.x * 4;
    const float* W = (row0 < NDRUG) ? drug_w : dis_w;
    for (int i = threadIdx.x; i < 4096; i += 256) w[i] = W[i];
    int r = threadIdx.x >> 6, d = threadIdx.x & 63;
    int row = row0 + r;
    fr[r * 64 + d] = (row0 < NDRUG) ? drug_f[(size_t)row * 64 + d]
                                    : dis_f[(size_t)(row - NDRUG) * 64 + d];
    __syncthreads();
    float acc = 0.f;
    #pragma unroll 16
    for (int k = 0; k < 64; k++) acc += fr[r * 64 + k] * w[k * 64 + d];
    g_xn[(size_t)row * 64 + d] = acc * g_norm[row];
}

// ===== K3: target += (graph @ xn) * row_norm. grid (96,3), block 256 =====
__global__ __launch_bounds__(256) void k_spmm(const float* __restrict__ graph) {
    __shared__ __align__(16) float As[64 * 33];
    __shared__ __align__(16) float Bs[32 * 72];
    int tx = threadIdx.x & 15, ty = threadIdx.x >> 4;
    int rowbase = blockIdx.x * 64;
    int kstart = blockIdx.y * 2048, kend = kstart + 2048;
    float acc[4][4];
    #pragma unroll
    for (int i = 0; i < 4; i++)
        #pragma unroll
        for (int j = 0; j < 4; j++) acc[i][j] = 0.f;
    int alr = threadIdx.x >> 2, alk = (threadIdx.x & 3) * 8;
    int bbk = threadIdx.x >> 3, bbc = (threadIdx.x & 7) * 8;
    for (int kb = kstart; kb < kend; kb += 32) {
        float4 a0 = *reinterpret_cast<const float4*>(graph + (size_t)(rowbase + alr) * NN + kb + alk);
        float4 a1 = *reinterpret_cast<const float4*>(graph + (size_t)(rowbase + alr) * NN + kb + alk + 4);
        float4 b0 = *reinterpret_cast<const float4*>(g_xn + (size_t)(kb + bbk) * 64 + bbc);
        float4 b1 = *reinterpret_cast<const float4*>(g_xn + (size_t)(kb + bbk) * 64 + bbc + 4);
        As[alr * 33 + alk + 0] = a0.x; As[alr * 33 + alk + 1] = a0.y;
        As[alr * 33 + alk + 2] = a0.z; As[alr * 33 + alk + 3] = a0.w;
        As[alr * 33 + alk + 4] = a1.x; As[alr * 33 + alk + 5] = a1.y;
        As[alr * 33 + alk + 6] = a1.z; As[alr * 33 + alk + 7] = a1.w;
        *reinterpret_cast<float4*>(Bs + bbk * 72 + bbc)     = b0;
        *reinterpret_cast<float4*>(Bs + bbk * 72 + bbc + 4) = b1;
        __syncthreads();
        #pragma unroll 8
        for (int kk = 0; kk < 32; kk++) {
            float a_0 = As[ty * 33 + kk];
            float a_1 = As[(ty + 16) * 33 + kk];
            float a_2 = As[(ty + 32) * 33 + kk];
            float a_3 = As[(ty + 48) * 33 + kk];
            float4 b = *reinterpret_cast<const float4*>(Bs + kk * 72 + tx * 4);
            acc[0][0] += a_0 * b.x; acc[0][1] += a_0 * b.y; acc[0][2] += a_0 * b.z; acc[0][3] += a_0 * b.w;
            acc[1][0] += a_1 * b.x; acc[1][1] += a_1 * b.y; acc[1][2] += a_1 * b.z; acc[1][3] += a_1 * b.w;
            acc[2][0] += a_2 * b.x; acc[2][1] += a_2 * b.y; acc[2][2] += a_2 * b.z; acc[2][3] += a_2 * b.w;
            acc[3][0] += a_3 * b.x; acc[3][1] += a_3 * b.y; acc[3][2] += a_3 * b.z; acc[3][3] += a_3 * b.w;
        }
        __syncthreads();
    }
    #pragma unroll
    for (int i = 0; i < 4; i++) {
        int row = rowbase + ty + 16 * i;
        float nr = g_norm[row];
        float* tp = &g_target[(size_t)row * 64 + tx * 4];
        #pragma unroll
        for (int j = 0; j < 4; j++) atomicAdd(tp + j, acc[i][j] * nr);
    }
}

// ===== K4: time embedding + MLP -> aux. grid 384, block 256, 16 nodes/CTA =====
__global__ __launch_bounds__(256) void k_mlp(const int* __restrict__ tsteps,
                                             const float* __restrict__ emb_w, const float* __restrict__ emb_b,
                                             const float* __restrict__ in_w,  const float* __restrict__ in_b,
                                             const float* __restrict__ out_w, const float* __restrict__ out_b) {
    __shared__ float cs[16 * 81];
    __shared__ float hs[16 * 257];
    int tid = threadIdx.x;
    int base = blockIdx.x * 16;
    for (int idx = tid; idx < 16 * 64; idx += 256) {
        int n = idx >> 6, d = idx & 63;
        cs[n * 81 + d] = g_target[(size_t)(base + n) * 64 + d];
    }
    {   // 16 nodes x 16 emb = 256 = blockDim
        int n = tid >> 4, e = tid & 15;
        float t = (float)tsteps[base + n];
        float acc = emb_b[e];
        for (int k = 0; k < 16; k++) {
            int j = k & 7;
            float fr = expf(-1.15129254649702f * (float)j);
            float te = (k < 8) ? cosf(t * fr) : sinf(t * fr);
            acc += te * emb_w[k * 16 + e];
        }
        cs[n * 81 + 64 + e] = acc;
    }
    __syncthreads();
    {   // hidden unit j = tid for 16 nodes
        float acc[16];
        #pragma unroll
        for (int n = 0; n < 16; n++) acc[n] = 0.f;
        for (int k = 0; k < 80; k++) {
            float w = in_w[k * 256 + tid];
            #pragma unroll
            for (int n = 0; n < 16; n++) acc[n] += cs[n * 81 + k] * w;
        }
        float bj = in_b[tid];
        #pragma unroll
        for (int n = 0; n < 16; n++) hs[n * 257 + tid] = tanhf(acc[n] + bj);
    }
    __syncthreads();
    {   // output: column d for 4 nodes each
        int d = tid & 63, gg = tid >> 6;
        float oa[4];
        #pragma unroll
        for (int nn = 0; nn < 4; nn++) oa[nn] = 0.f;
        for (int k = 0; k < 256; k++) {
            float w = out_w[k * 64 + d];
            #pragma unroll
            for (int nn = 0; nn < 4; nn++) oa[nn] += hs[(gg * 4 + nn) * 257 + k] * w;
        }
        float bd = out_b[d];
        #pragma unroll
        for (int nn = 0; nn < 4; nn++)
            g_aux[(size_t)(base + gg * 4 + nn) * 64 + d] = oa[nn] + bd;
    }
}

// ===== K5: q/k/v projections (head-major). grid 1536, block 256 =====
__global__ __launch_bounds__(256) void k_qkv(const float* __restrict__ wq, const float* __restrict__ bq,
                                             const float* __restrict__ wk, const float* __restrict__ bk,
                                             const float* __restrict__ wv, const float* __restrict__ bv) {
    __shared__ float w[4096];
    __shared__ float st[256], sa[256];
    int r = threadIdx.x >> 6, d = threadIdx.x & 63;
    int row = blockIdx.x * 4 + r;
    st[r * 64 + d] = g_target[(size_t)row * 64 + d];
    sa[r * 64 + d] = g_aux[(size_t)row * 64 + d];
    int h = d >> 4, hd = d & 15;
    size_t oidx = ((size_t)h * NN + row) * 16 + hd;

    for (int i = threadIdx.x; i < 4096; i += 256) w[i] = wq[i];
    __syncthreads();
    float acc = bq[d];
    #pragma unroll 16
    for (int k = 0; k < 64; k++) acc += st[r * 64 + k] * w[k * 64 + d];
    g_q[oidx] = acc;
    __syncthreads();

    for (int i = threadIdx.x; i < 4096; i += 256) w[i] = wk[i];
    __syncthreads();
    acc = bk[d];
    #pragma unroll 16
    for (int k = 0; k < 64; k++) acc += sa[r * 64 + k] * w[k * 64 + d];
    g_k[oidx] = acc;
    __syncthreads();

    for (int i = threadIdx.x; i < 4096; i += 256) w[i] = wv[i];
    __syncthreads();
    acc = bv[d];
    #pragma unroll 16
    for (int k = 0; k < 64; k++) acc += sa[r * 64 + k] * w[k * 64 + d];
    g_v[oidx] = acc;
}

// ===== K6: attention via tf32 mma.sync. grid (48,4,3), block 128 =====
// Warp handles 32 queries; V padded with a ones-column so l comes from the PV mma.
#define KS_STR 20
#define VS_STR 25
#define PB_STR 68
__global__ __launch_bounds__(128) void k_attn() {
    __shared__ float Ks[64 * KS_STR];            // K block [64 keys][16]
    __shared__ float Vsb[64 * VS_STR];           // V block [64 keys][24+pad], col16=1, 17+=0
    __shared__ float Psm[4 * 32 * PB_STR];       // per-warp P [32 q][64 keys]
    int tid = threadIdx.x;
    int w = tid >> 5, lane = tid & 31;
    int g = lane >> 2, t = lane & 3;
    int h = blockIdx.y;
    int qn0 = blockIdx.x * 128 + w * 32;
    float* Pb = Psm + w * 32 * PB_STR;

    // init constant V columns (16..24)
    for (int idx = tid; idx < 64 * 9; idx += 128) {
        int row = idx / 9, c = 16 + idx % 9;
        Vsb[row * VS_STR + c] = (c == 16) ? 1.0f : 0.0f;
    }

    // Q fragments (scale 0.25 folded in)
    const float* qb = g_q + ((size_t)h * NN + qn0) * 16;
    unsigned aq[2][2][4];
    #pragma unroll
    for (int mt = 0; mt < 2; mt++)
        #pragma unroll
        for (int kc = 0; kc < 2; kc++) {
            aq[mt][kc][0] = __float_as_uint(0.25f * qb[(mt * 16 + g) * 16 + kc * 8 + t]);
            aq[mt][kc][1] = __float_as_uint(0.25f * qb[(mt * 16 + g + 8) * 16 + kc * 8 + t]);
            aq[mt][kc][2] = __float_as_uint(0.25f * qb[(mt * 16 + g) * 16 + kc * 8 + t + 4]);
            aq[mt][kc][3] = __float_as_uint(0.25f * qb[(mt * 16 + g + 8) * 16 + kc * 8 + t + 4]);
        }

    float o[2][3][4];
    #pragma unroll
    for (int mt = 0; mt < 2; mt++)
        #pragma unroll
        for (int nt = 0; nt < 3; nt++)
            #pragma unroll
            for (int i = 0; i < 4; i++) o[mt][nt][i] = 0.f;

    int kbase = blockIdx.z * 2048;
    int krow = tid >> 1, kpart = tid & 1;   // cooperative loader: 2 threads/key
    for (int c0 = 0; c0 < 2048; c0 += 64) {
        __syncthreads();
        {
            int key = kbase + c0 + krow;
            const float* kp = g_k + ((size_t)h * NN + key) * 16 + kpart * 8;
            const float* vp = g_v + ((size_t)h * NN + key) * 16 + kpart * 8;
            float4 k0 = *reinterpret_cast<const float4*>(kp);
            float4 k1 = *reinterpret_cast<const float4*>(kp + 4);
            float4 v0 = *reinterpret_cast<const float4*>(vp);
            float4 v1 = *reinterpret_cast<const float4*>(vp + 4);
            float* kd = Ks + krow * KS_STR + kpart * 8;
            kd[0] = k0.x; kd[1] = k0.y; kd[2] = k0.z; kd[3] = k0.w;
            kd[4] = k1.x; kd[5] = k1.y; kd[6] = k1.z; kd[7] = k1.w;
            float* vd = Vsb + krow * VS_STR + kpart * 8;
            vd[0] = v0.x; vd[1] = v0.y; vd[2] = v0.z; vd[3] = v0.w;
            vd[4] = v1.x; vd[5] = v1.y; vd[6] = v1.z; vd[7] = v1.w;
        }
        __syncthreads();

        // S = Q K^T (pre-scaled)
        float d[2][8][4];
        #pragma unroll
        for (int mt = 0; mt < 2; mt++)
            #pragma unroll
            for (int nt = 0; nt < 8; nt++)
                #pragma unroll
                for (int i = 0; i < 4; i++) d[mt][nt][i] = 0.f;
        #pragma unroll
        for (int kc = 0; kc < 2; kc++)
            #pragma unroll
            for (int nt = 0; nt < 8; nt++) {
                unsigned b0 = __float_as_uint(Ks[(nt * 8 + g) * KS_STR + kc * 8 + t]);
                unsigned b1 = __float_as_uint(Ks[(nt * 8 + g) * KS_STR + kc * 8 + t + 4]);
                MMA_TF32(d[0][nt], aq[0][kc], b0, b1);
                MMA_TF32(d[1][nt], aq[1][kc], b0, b1);
            }

        // P = exp(S) -> per-warp smem buffer
        #pragma unroll
        for (int mt = 0; mt < 2; mt++)
            #pragma unroll
            for (int nt = 0; nt < 8; nt++) {
                float2 p01, p23;
                p01.x = __expf(d[mt][nt][0]); p01.y = __expf(d[mt][nt][1]);
                p23.x = __expf(d[mt][nt][2]); p23.y = __expf(d[mt][nt][3]);
                int col = nt * 8 + 2 * t;
                *reinterpret_cast<float2*>(Pb + (mt * 16 + g) * PB_STR + col) = p01;
                *reinterpret_cast<float2*>(Pb + (mt * 16 + g + 8) * PB_STR + col) = p23;
            }
        __syncwarp();

        // O += P V  (col 16 of V is ones -> l)
        #pragma unroll
        for (int kc = 0; kc < 8; kc++) {
            unsigned pa[2][4];
            #pragma unroll
            for (int mt = 0; mt < 2; mt++) {
                pa[mt][0] = __float_as_uint(Pb[(mt * 16 + g) * PB_STR + kc * 8 + t]);
                pa[mt][1] = __float_as_uint(Pb[(mt * 16 + g + 8) * PB_STR + kc * 8 + t]);
                pa[mt][2] = __float_as_uint(Pb[(mt * 16 + g) * PB_STR + kc * 8 + t + 4]);
                pa[mt][3] = __float_as_uint(Pb[(mt * 16 + g + 8) * PB_STR + kc * 8 + t + 4]);
            }
            #pragma unroll
            for (int nt = 0; nt < 3; nt++) {
                unsigned b0 = __float_as_uint(Vsb[(kc * 8 + t) * VS_STR + nt * 8 + g]);
                unsigned b1 = __float_as_uint(Vsb[(kc * 8 + t + 4) * VS_STR + nt * 8 + g]);
                MMA_TF32(o[0][nt], pa[0], b0, b1);
                MMA_TF32(o[1][nt], pa[1], b0, b1);
            }
        }
        __syncwarp();
    }

    // merge partials
    #pragma unroll
    for (int mt = 0; mt < 2; mt++) {
        int r0 = qn0 + mt * 16 + g, r1 = r0 + 8;
        #pragma unroll
        for (int nt = 0; nt < 2; nt++) {
            int c = h * 16 + nt * 8 + 2 * t;
            atomicAdd(&g_oacc[(size_t)r0 * 64 + c],     o[mt][nt][0]);
            atomicAdd(&g_oacc[(size_t)r0 * 64 + c + 1], o[mt][nt][1]);
            atomicAdd(&g_oacc[(size_t)r1 * 64 + c],     o[mt][nt][2]);
            atomicAdd(&g_oacc[(size_t)r1 * 64 + c + 1], o[mt][nt][3]);
        }
        if (t == 0) {
            atomicAdd(&g_lacc[r0 * 4 + h], o[mt][2][0]);
            atomicAdd(&g_lacc[r1 * 4 + h], o[mt][2][2]);
        }
    }
}

// ===== K7: wo proj + fuse + residual LN -> out. grid 1536, block 256 =====
__global__ __launch_bounds__(256) void k_final(const float* __restrict__ wo, const float* __restrict__ bo,
                                               const float* __restrict__ fuse_w, const float* __restrict__ fuse_b,
                                               const float* __restrict__ ln_g, const float* __restrict__ ln_b,
                                               float* __restrict__ out) {
    __shared__ float w[4096];
    __shared__ float st[256], sao[256], sy[256];
    int r = threadIdx.x >> 6, d = threadIdx.x & 63;
    int row = blockIdx.x * 4 + r;
    st[r * 64 + d] = g_target[(size_t)row * 64 + d];
    float lh = g_lacc[row * 4 + (d >> 4)];
    sy[r * 64 + d] = g_oacc[(size_t)row * 64 + d] / lh;
    for (int i = threadIdx.x; i < 4096; i += 256) w[i] = wo[i];
    __syncthreads();
    float acc = bo[d];
    #pragma unroll 16
    for (int k = 0; k < 64; k++) acc += sy[r * 64 + k] * w[k * 64 + d];
    __syncthreads();
    sao[r * 64 + d] = acc;
    for (int i = threadIdx.x; i < 4096; i += 256) w[i] = fuse_w[i];
    __syncthreads();
    float f = fuse_b[d];
    #pragma unroll 16
    for (int k = 0; k < 64; k++) f += st[r * 64 + k] * w[k * 64 + d];
    __syncthreads();
    for (int i = threadIdx.x; i < 4096; i += 256) w[i] = fuse_w[4096 + i];
    __syncthreads();
    #pragma unroll 16
    for (int k = 0; k < 64; k++) f += sao[r * 64 + k] * w[k * 64 + d];
    float y = f + st[r * 64 + d];
    __syncthreads();
    sy[r * 64 + d] = y;
    __syncthreads();
    float mu = 0.f;
    #pragma unroll 16
    for (int k = 0; k < 64; k++) mu += sy[r * 64 + k];
    mu *= (1.0f / 64.0f);
    float var = 0.f;
    #pragma unroll 16
    for (int k = 0; k < 64; k++) { float tt = sy[r * 64 + k] - mu; var += tt * tt; }
    var *= (1.0f / 64.0f);
    out[(size_t)row * 64 + d] = (y - mu) * rsqrtf(var + 1e-5f) * ln_g[d] + ln_b[d];
}

extern "C" void kernel_launch(void* const* d_in, const int* in_sizes, int n_in,
                              void* d_out, int out_size) {
    const float* graph     = (const float*)d_in[0];
    const float* drug_f    = (const float*)d_in[1];
    const float* disease_f = (const float*)d_in[2];
    const int*   tsteps    = (const int*)  d_in[3];
    const float* drug_w    = (const float*)d_in[4];
    const float* disease_w = (const float*)d_in[5];
    const float* emb_w     = (const float*)d_in[6];
    const float* emb_b     = (const float*)d_in[7];
    const float* in_w      = (const float*)d_in[8];
    const float* in_b      = (const float*)d_in[9];
    const float* out_w     = (const float*)d_in[10];
    const float* out_b     = (const float*)d_in[11];
    const float* wq = (const float*)d_in[12]; const float* bq = (const float*)d_in[13];
    const float* wk = (const float*)d_in[14]; const float* bk = (const float*)d_in[15];
    const float* wv = (const float*)d_in[16]; const float* bv = (const float*)d_in[17];
    const float* wo = (const float*)d_in[18]; const float* bo = (const float*)d_in[19];
    const float* fuse_w = (const float*)d_in[20]; const float* fuse_b = (const float*)d_in[21];
    const float* ln_g   = (const float*)d_in[22]; const float* ln_b   = (const float*)d_in[23];
    float* out = (float*)d_out;

    k_deg  <<<768, 256>>>(graph);
    k_proj <<<1536, 256>>>(drug_f, disease_f, drug_w, disease_w);
    k_spmm <<<dim3(96, 3), 256>>>(graph);
    k_mlp  <<<384, 256>>>(tsteps, emb_w, emb_b, in_w, in_b, out_w, out_b);
    k_qkv  <<<1536, 256>>>(wq, bq, wk, bk, wv, bv);
    k_attn <<<dim3(48, 4, 3), 128>>>();
    k_final<<<1536, 256>>>(wo, bo, fuse_w, fuse_b, ln_g, ln_b, out);
}

// round 9
// speedup vs baseline: 1.9178x; 1.2220x over previous
#include <cuda_runtime.h>
#include <math.h>

#define NN 6144
#define NDRUG 3072

// ---------- scratch (device globals; no allocation allowed) ----------
__device__ __align__(16) float g_norm[NN];
__device__ __align__(16) float g_xn[NN * 64];
__device__ __align__(16) float g_target[NN * 64];
__device__ __align__(16) float g_aux[NN * 64];
__device__ __align__(16) float g_q[4 * NN * 16];    // head-major
__device__ __align__(16) float g_k[4 * NN * 16];
__device__ __align__(16) float g_v[4 * NN * 16];
__device__ __align__(16) float g_oacc[NN * 64];
__device__ __align__(16) float g_lacc[NN * 4];

#define MMA_TF32(D, A, B0, B1) \
    asm volatile("mma.sync.aligned.m16n8k8.row.col.f32.tf32.tf32.f32 " \
                 "{%0,%1,%2,%3},{%4,%5,%6,%7},{%8,%9},{%0,%1,%2,%3};" \
                 : "+f"((D)[0]), "+f"((D)[1]), "+f"((D)[2]), "+f"((D)[3]) \
                 : "r"((A)[0]), "r"((A)[1]), "r"((A)[2]), "r"((A)[3]), "r"(B0), "r"(B1))

// ===== K1: degree norms + zero atomic accumulators. grid 768, block 256 =====
__global__ __launch_bounds__(256) void k_deg(const float* __restrict__ graph) {
    int wid = threadIdx.x >> 5, lane = threadIdx.x & 31;
    int row = blockIdx.x * 8 + wid;
    const float4* gr = reinterpret_cast<const float4*>(graph + (size_t)row * NN);
    float s = 0.f;
    #pragma unroll 4
    for (int i = lane; i < NN / 4; i += 32) { float4 t = gr[i]; s += (t.x + t.y) + (t.z + t.w); }
    #pragma unroll
    for (int o = 16; o; o >>= 1) s += __shfl_xor_sync(0xffffffffu, s, o);
    if (lane == 0) g_norm[row] = rsqrtf(fmaxf(s, 1.0f));
    int t = blockIdx.x * 256 + threadIdx.x;
    g_target[t] = 0.f; g_target[t + 196608] = 0.f;
    g_oacc[t] = 0.f;   g_oacc[t + 196608] = 0.f;
    if (t < NN * 4) g_lacc[t] = 0.f;
}

// ===== K2: per-type projection scaled by column norm. grid 1536, block 256 =====
__global__ __launch_bounds__(256) void k_proj(const float* __restrict__ drug_f,
                                              const float* __restrict__ dis_f,
                                              const float* __restrict__ drug_w,
                                              const float* __restrict__ dis_w) {
    __shared__ float w[4096];
    __shared__ float fr[256];
    int row0 = blockIdx.x * 4;
    const float* W = (row0 < NDRUG) ? drug_w : dis_w;
    for (int i = threadIdx.x; i < 4096; i += 256) w[i] = W[i];
    int r = threadIdx.x >> 6, d = threadIdx.x & 63;
    int row = row0 + r;
    fr[r * 64 + d] = (row0 < NDRUG) ? drug_f[(size_t)row * 64 + d]
                                    : dis_f[(size_t)(row - NDRUG) * 64 + d];
    __syncthreads();
    float acc = 0.f;
    #pragma unroll 16
    for (int k = 0; k < 64; k++) acc += fr[r * 64 + k] * w[k * 64 + d];
    g_xn[(size_t)row * 64 + d] = acc * g_norm[row];
}

// ===== K3: target += (graph @ xn) * row_norm via tf32 mma. grid (48,3), block 256 =====
#define AST 36
#define BST 72
__global__ __launch_bounds__(256) void k_spmm(const float* __restrict__ graph) {
    __shared__ __align__(16) float As[128 * AST];
    __shared__ __align__(16) float Bs[32 * BST];
    int tid = threadIdx.x;
    int w = tid >> 5, lane = tid & 31, g = lane >> 2, t = lane & 3;
    int rowbase = blockIdx.x * 128;
    int kstart = blockIdx.y * 2048;

    float o[8][4];
    #pragma unroll
    for (int nt = 0; nt < 8; nt++)
        #pragma unroll
        for (int i = 0; i < 4; i++) o[nt][i] = 0.f;

    int ar = tid >> 1, ac = (tid & 1) * 16;   // A loader: 16 floats/thread
    int br = tid >> 3, bc = (tid & 7) * 8;    // B loader: 8 floats/thread

    for (int kb = 0; kb < 2048; kb += 32) {
        const float* gp = graph + (size_t)(rowbase + ar) * NN + kstart + kb + ac;
        float4 a0 = *reinterpret_cast<const float4*>(gp);
        float4 a1 = *reinterpret_cast<const float4*>(gp + 4);
        float4 a2 = *reinterpret_cast<const float4*>(gp + 8);
        float4 a3 = *reinterpret_cast<const float4*>(gp + 12);
        const float* bp = g_xn + (size_t)(kstart + kb + br) * 64 + bc;
        float4 b0 = *reinterpret_cast<const float4*>(bp);
        float4 b1 = *reinterpret_cast<const float4*>(bp + 4);
        __syncthreads();
        *reinterpret_cast<float4*>(As + ar * AST + ac)      = a0;
        *reinterpret_cast<float4*>(As + ar * AST + ac + 4)  = a1;
        *reinterpret_cast<float4*>(As + ar * AST + ac + 8)  = a2;
        *reinterpret_cast<float4*>(As + ar * AST + ac + 12) = a3;
        *reinterpret_cast<float4*>(Bs + br * BST + bc)     = b0;
        *reinterpret_cast<float4*>(Bs + br * BST + bc + 4) = b1;
        __syncthreads();
        #pragma unroll
        for (int kc = 0; kc < 4; kc++) {
            unsigned a[4];
            a[0] = __float_as_uint(As[(w * 16 + g) * AST + kc * 8 + t]);
            a[1] = __float_as_uint(As[(w * 16 + g + 8) * AST + kc * 8 + t]);
            a[2] = __float_as_uint(As[(w * 16 + g) * AST + kc * 8 + t + 4]);
            a[3] = __float_as_uint(As[(w * 16 + g + 8) * AST + kc * 8 + t + 4]);
            #pragma unroll
            for (int nt = 0; nt < 8; nt++) {
                unsigned bb0 = __float_as_uint(Bs[(kc * 8 + t) * BST + nt * 8 + g]);
                unsigned bb1 = __float_as_uint(Bs[(kc * 8 + t + 4) * BST + nt * 8 + g]);
                MMA_TF32(o[nt], a, bb0, bb1);
            }
        }
    }
    int r0 = rowbase + w * 16 + g, r1 = r0 + 8;
    float n0 = g_norm[r0], n1 = g_norm[r1];
    #pragma unroll
    for (int nt = 0; nt < 8; nt++) {
        int c = nt * 8 + 2 * t;
        atomicAdd(&g_target[(size_t)r0 * 64 + c],     o[nt][0] * n0);
        atomicAdd(&g_target[(size_t)r0 * 64 + c + 1], o[nt][1] * n0);
        atomicAdd(&g_target[(size_t)r1 * 64 + c],     o[nt][2] * n1);
        atomicAdd(&g_target[(size_t)r1 * 64 + c + 1], o[nt][3] * n1);
    }
}

// ===== K4: time embedding + MLP -> aux. grid 384, block 256, dyn smem 169088 B =====
__global__ __launch_bounds__(256) void k_mlp(const int* __restrict__ tsteps,
                                             const float* __restrict__ emb_w, const float* __restrict__ emb_b,
                                             const float* __restrict__ in_w,  const float* __restrict__ in_b,
                                             const float* __restrict__ out_w, const float* __restrict__ out_b) {
    extern __shared__ float smp[];
    float* s_inw  = smp;                 // 80*256 = 20480
    float* s_outw = smp + 20480;         // 256*64 = 16384
    float* cs     = smp + 36864;         // 16*81  = 1296
    float* hs     = smp + 38160;         // 16*257 = 4112
    int tid = threadIdx.x;
    int base = blockIdx.x * 16;
    // bulk weight staging (pipelined float4 LDGs)
    for (int i = tid; i < 20480 / 4; i += 256)
        reinterpret_cast<float4*>(s_inw)[i] = reinterpret_cast<const float4*>(in_w)[i];
    for (int i = tid; i < 16384 / 4; i += 256)
        reinterpret_cast<float4*>(s_outw)[i] = reinterpret_cast<const float4*>(out_w)[i];
    for (int idx = tid; idx < 16 * 64; idx += 256) {
        int n = idx >> 6, d = idx & 63;
        cs[n * 81 + d] = g_target[(size_t)(base + n) * 64 + d];
    }
    {   // 16 nodes x 16 emb = 256 = blockDim
        int n = tid >> 4, e = tid & 15;
        float t = (float)tsteps[base + n];
        float acc = emb_b[e];
        for (int k = 0; k < 16; k++) {
            int j = k & 7;
            float fr = expf(-1.15129254649702f * (float)j);
            float te = (k < 8) ? cosf(t * fr) : sinf(t * fr);
            acc += te * emb_w[k * 16 + e];
        }
        cs[n * 81 + 64 + e] = acc;
    }
    __syncthreads();
    {   // hidden unit j = tid for 16 nodes; all operands in smem
        float acc[16];
        #pragma unroll
        for (int n = 0; n < 16; n++) acc[n] = 0.f;
        #pragma unroll 4
        for (int k = 0; k < 80; k++) {
            float w = s_inw[k * 256 + tid];
            #pragma unroll
            for (int n = 0; n < 16; n++) acc[n] += cs[n * 81 + k] * w;
        }
        float bj = in_b[tid];
        #pragma unroll
        for (int n = 0; n < 16; n++) hs[n * 257 + tid] = tanhf(acc[n] + bj);
    }
    __syncthreads();
    {   // output: column d for 4 nodes each
        int d = tid & 63, gg = tid >> 6;
        float oa[4];
        #pragma unroll
        for (int nn = 0; nn < 4; nn++) oa[nn] = 0.f;
        #pragma unroll 4
        for (int k = 0; k < 256; k++) {
            float w = s_outw[k * 64 + d];
            #pragma unroll
            for (int nn = 0; nn < 4; nn++) oa[nn] += hs[(gg * 4 + nn) * 257 + k] * w;
        }
        float bd = out_b[d];
        #pragma unroll
        for (int nn = 0; nn < 4; nn++)
            g_aux[(size_t)(base + gg * 4 + nn) * 64 + d] = oa[nn] + bd;
    }
}

// ===== K5: q/k/v projections (head-major). grid 1536, block 256 =====
__global__ __launch_bounds__(256) void k_qkv(const float* __restrict__ wq, const float* __restrict__ bq,
                                             const float* __restrict__ wk, const float* __restrict__ bk,
                                             const float* __restrict__ wv, const float* __restrict__ bv) {
    __shared__ float w[4096];
    __shared__ float st[256], sa[256];
    int r = threadIdx.x >> 6, d = threadIdx.x & 63;
    int row = blockIdx.x * 4 + r;
    st[r * 64 + d] = g_target[(size_t)row * 64 + d];
    sa[r * 64 + d] = g_aux[(size_t)row * 64 + d];
    int h = d >> 4, hd = d & 15;
    size_t oidx = ((size_t)h * NN + row) * 16 + hd;

    for (int i = threadIdx.x; i < 4096; i += 256) w[i] = wq[i];
    __syncthreads();
    float acc = bq[d];
    #pragma unroll 16
    for (int k = 0; k < 64; k++) acc += st[r * 64 + k] * w[k * 64 + d];
    g_q[oidx] = acc;
    __syncthreads();

    for (int i = threadIdx.x; i < 4096; i += 256) w[i] = wk[i];
    __syncthreads();
    acc = bk[d];
    #pragma unroll 16
    for (int k = 0; k < 64; k++) acc += sa[r * 64 + k] * w[k * 64 + d];
    g_k[oidx] = acc;
    __syncthreads();

    for (int i = threadIdx.x; i < 4096; i += 256) w[i] = wv[i];
    __syncthreads();
    acc = bv[d];
    #pragma unroll 16
    for (int k = 0; k < 64; k++) acc += sa[r * 64 + k] * w[k * 64 + d];
    g_v[oidx] = acc;
}

// ===== K6: attention via tf32 mma.sync. grid (48,4,3), block 128 =====
#define KS_STR 20
#define VS_STR 25
#define PB_STR 68
__global__ __launch_bounds__(128) void k_attn() {
    __shared__ float Ks[64 * KS_STR];
    __shared__ float Vsb[64 * VS_STR];
    __shared__ float Psm[4 * 32 * PB_STR];
    int tid = threadIdx.x;
    int w = tid >> 5, lane = tid & 31;
    int g = lane >> 2, t = lane & 3;
    int h = blockIdx.y;
    int qn0 = blockIdx.x * 128 + w * 32;
    float* Pb = Psm + w * 32 * PB_STR;

    for (int idx = tid; idx < 64 * 9; idx += 128) {
        int row = idx / 9, c = 16 + idx % 9;
        Vsb[row * VS_STR + c] = (c == 16) ? 1.0f : 0.0f;
    }

    const float* qb = g_q + ((size_t)h * NN + qn0) * 16;
    unsigned aq[2][2][4];
    #pragma unroll
    for (int mt = 0; mt < 2; mt++)
        #pragma unroll
        for (int kc = 0; kc < 2; kc++) {
            aq[mt][kc][0] = __float_as_uint(0.25f * qb[(mt * 16 + g) * 16 + kc * 8 + t]);
            aq[mt][kc][1] = __float_as_uint(0.25f * qb[(mt * 16 + g + 8) * 16 + kc * 8 + t]);
            aq[mt][kc][2] = __float_as_uint(0.25f * qb[(mt * 16 + g) * 16 + kc * 8 + t + 4]);
            aq[mt][kc][3] = __float_as_uint(0.25f * qb[(mt * 16 + g + 8) * 16 + kc * 8 + t + 4]);
        }

    float o[2][3][4];
    #pragma unroll
    for (int mt = 0; mt < 2; mt++)
        #pragma unroll
        for (int nt = 0; nt < 3; nt++)
            #pragma unroll
            for (int i = 0; i < 4; i++) o[mt][nt][i] = 0.f;

    int kbase = blockIdx.z * 2048;
    int krow = tid >> 1, kpart = tid & 1;
    for (int c0 = 0; c0 < 2048; c0 += 64) {
        __syncthreads();
        {
            int key = kbase + c0 + krow;
            const float* kp = g_k + ((size_t)h * NN + key) * 16 + kpart * 8;
            const float* vp = g_v + ((size_t)h * NN + key) * 16 + kpart * 8;
            float4 k0 = *reinterpret_cast<const float4*>(kp);
            float4 k1 = *reinterpret_cast<const float4*>(kp + 4);
            float4 v0 = *reinterpret_cast<const float4*>(vp);
            float4 v1 = *reinterpret_cast<const float4*>(vp + 4);
            float* kd = Ks + krow * KS_STR + kpart * 8;
            kd[0] = k0.x; kd[1] = k0.y; kd[2] = k0.z; kd[3] = k0.w;
            kd[4] = k1.x; kd[5] = k1.y; kd[6] = k1.z; kd[7] = k1.w;
            float* vd = Vsb + krow * VS_STR + kpart * 8;
            vd[0] = v0.x; vd[1] = v0.y; vd[2] = v0.z; vd[3] = v0.w;
            vd[4] = v1.x; vd[5] = v1.y; vd[6] = v1.z; vd[7] = v1.w;
        }
        __syncthreads();

        float d[2][8][4];
        #pragma unroll
        for (int mt = 0; mt < 2; mt++)
            #pragma unroll
            for (int nt = 0; nt < 8; nt++)
                #pragma unroll
                for (int i = 0; i < 4; i++) d[mt][nt][i] = 0.f;
        #pragma unroll
        for (int kc = 0; kc < 2; kc++)
            #pragma unroll
            for (int nt = 0; nt < 8; nt++) {
                unsigned b0 = __float_as_uint(Ks[(nt * 8 + g) * KS_STR + kc * 8 + t]);
                unsigned b1 = __float_as_uint(Ks[(nt * 8 + g) * KS_STR + kc * 8 + t + 4]);
                MMA_TF32(d[0][nt], aq[0][kc], b0, b1);
                MMA_TF32(d[1][nt], aq[1][kc], b0, b1);
            }

        #pragma unroll
        for (int mt = 0; mt < 2; mt++)
            #pragma unroll
            for (int nt = 0; nt < 8; nt++) {
                float2 p01, p23;
                p01.x = __expf(d[mt][nt][0]); p01.y = __expf(d[mt][nt][1]);
                p23.x = __expf(d[mt][nt][2]); p23.y = __expf(d[mt][nt][3]);
                int col = nt * 8 + 2 * t;
                *reinterpret_cast<float2*>(Pb + (mt * 16 + g) * PB_STR + col) = p01;
                *reinterpret_cast<float2*>(Pb + (mt * 16 + g + 8) * PB_STR + col) = p23;
            }
        __syncwarp();

        #pragma unroll
        for (int kc = 0; kc < 8; kc++) {
            unsigned pa[2][4];
            #pragma unroll
            for (int mt = 0; mt < 2; mt++) {
                pa[mt][0] = __float_as_uint(Pb[(mt * 16 + g) * PB_STR + kc * 8 + t]);
                pa[mt][1] = __float_as_uint(Pb[(mt * 16 + g + 8) * PB_STR + kc * 8 + t]);
                pa[mt][2] = __float_as_uint(Pb[(mt * 16 + g) * PB_STR + kc * 8 + t + 4]);
                pa[mt][3] = __float_as_uint(Pb[(mt * 16 + g + 8) * PB_STR + kc * 8 + t + 4]);
            }
            #pragma unroll
            for (int nt = 0; nt < 3; nt++) {
                unsigned b0 = __float_as_uint(Vsb[(kc * 8 + t) * VS_STR + nt * 8 + g]);
                unsigned b1 = __float_as_uint(Vsb[(kc * 8 + t + 4) * VS_STR + nt * 8 + g]);
                MMA_TF32(o[0][nt], pa[0], b0, b1);
                MMA_TF32(o[1][nt], pa[1], b0, b1);
            }
        }
        __syncwarp();
    }

    #pragma unroll
    for (int mt = 0; mt < 2; mt++) {
        int r0 = qn0 + mt * 16 + g, r1 = r0 + 8;
        #pragma unroll
        for (int nt = 0; nt < 2; nt++) {
            int c = h * 16 + nt * 8 + 2 * t;
            atomicAdd(&g_oacc[(size_t)r0 * 64 + c],     o[mt][nt][0]);
            atomicAdd(&g_oacc[(size_t)r0 * 64 + c + 1], o[mt][nt][1]);
            atomicAdd(&g_oacc[(size_t)r1 * 64 + c],     o[mt][nt][2]);
            atomicAdd(&g_oacc[(size_t)r1 * 64 + c + 1], o[mt][nt][3]);
        }
        if (t == 0) {
            atomicAdd(&g_lacc[r0 * 4 + h], o[mt][2][0]);
            atomicAdd(&g_lacc[r1 * 4 + h], o[mt][2][2]);
        }
    }
}

// ===== K7: wo proj + fuse + residual LN -> out. grid 1536, block 256 =====
__global__ __launch_bounds__(256) void k_final(const float* __restrict__ wo, const float* __restrict__ bo,
                                               const float* __restrict__ fuse_w, const float* __restrict__ fuse_b,
                                               const float* __restrict__ ln_g, const float* __restrict__ ln_b,
                                               float* __restrict__ out) {
    __shared__ float w[4096];
    __shared__ float st[256], sao[256], sy[256];
    int r = threadIdx.x >> 6, d = threadIdx.x & 63;
    int row = blockIdx.x * 4 + r;
    st[r * 64 + d] = g_target[(size_t)row * 64 + d];
    float lh = g_lacc[row * 4 + (d >> 4)];
    sy[r * 64 + d] = g_oacc[(size_t)row * 64 + d] / lh;
    for (int i = threadIdx.x; i < 4096; i += 256) w[i] = wo[i];
    __syncthreads();
    float acc = bo[d];
    #pragma unroll 16
    for (int k = 0; k < 64; k++) acc += sy[r * 64 + k] * w[k * 64 + d];
    __syncthreads();
    sao[r * 64 + d] = acc;
    for (int i = threadIdx.x; i < 4096; i += 256) w[i] = fuse_w[i];
    __syncthreads();
    float f = fuse_b[d];
    #pragma unroll 16
    for (int k = 0; k < 64; k++) f += st[r * 64 + k] * w[k * 64 + d];
    __syncthreads();
    for (int i = threadIdx.x; i < 4096; i += 256) w[i] = fuse_w[4096 + i];
    __syncthreads();
    #pragma unroll 16
    for (int k = 0; k < 64; k++) f += sao[r * 64 + k] * w[k * 64 + d];
    float y = f + st[r * 64 + d];
    __syncthreads();
    sy[r * 64 + d] = y;
    __syncthreads();
    float mu = 0.f;
    #pragma unroll 16
    for (int k = 0; k < 64; k++) mu += sy[r * 64 + k];
    mu *= (1.0f / 64.0f);
    float var = 0.f;
    #pragma unroll 16
    for (int k = 0; k < 64; k++) { float tt = sy[r * 64 + k] - mu; var += tt * tt; }
    var *= (1.0f / 64.0f);
    out[(size_t)row * 64 + d] = (y - mu) * rsqrtf(var + 1e-5f) * ln_g[d] + ln_b[d];
}

extern "C" void kernel_launch(void* const* d_in, const int* in_sizes, int n_in,
                              void* d_out, int out_size) {
    const float* graph     = (const float*)d_in[0];
    const float* drug_f    = (const float*)d_in[1];
    const float* disease_f = (const float*)d_in[2];
    const int*   tsteps    = (const int*)  d_in[3];
    const float* drug_w    = (const float*)d_in[4];
    const float* disease_w = (const float*)d_in[5];
    const float* emb_w     = (const float*)d_in[6];
    const float* emb_b     = (const float*)d_in[7];
    const float* in_w      = (const float*)d_in[8];
    const float* in_b      = (const float*)d_in[9];
    const float* out_w     = (const float*)d_in[10];
    const float* out_b     = (const float*)d_in[11];
    const float* wq = (const float*)d_in[12]; const float* bq = (const float*)d_in[13];
    const float* wk = (const float*)d_in[14]; const float* bk = (const float*)d_in[15];
    const float* wv = (const float*)d_in[16]; const float* bv = (const float*)d_in[17];
    const float* wo = (const float*)d_in[18]; const float* bo = (const float*)d_in[19];
    const float* fuse_w = (const float*)d_in[20]; const float* fuse_b = (const float*)d_in[21];
    const float* ln_g   = (const float*)d_in[22]; const float* ln_b   = (const float*)d_in[23];
    float* out = (float*)d_out;

    static int mlp_smem_set = 0;
    if (!mlp_smem_set) {
        cudaFuncSetAttribute(k_mlp, cudaFuncAttributeMaxDynamicSharedMemorySize, 169088);
        mlp_smem_set = 1;
    }

    k_deg  <<<768, 256>>>(graph);
    k_proj <<<1536, 256>>>(drug_f, disease_f, drug_w, disease_w);
    k_spmm <<<dim3(48, 3), 256>>>(graph);
    k_mlp  <<<384, 256, 169088>>>(tsteps, emb_w, emb_b, in_w, in_b, out_w, out_b);
    k_qkv  <<<1536, 256>>>(wq, bq, wk, bk, wv, bv);
    k_attn <<<dim3(48, 4, 3), 128>>>();
    k_final<<<1536, 256>>>(wo, bo, fuse_w, fuse_b, ln_g, ln_b, out);
}

// round 10
// speedup vs baseline: 2.1728x; 1.1330x over previous
#include <cuda_runtime.h>
#include <math.h>

#define NN 6144
#define NDRUG 3072

// ---------- scratch (device globals; no allocation allowed) ----------
__device__ __align__(16) float g_norm[NN];
__device__ __align__(16) float g_xn[NN * 64];
__device__ __align__(16) float g_target[NN * 64];
__device__ __align__(16) float g_aux[NN * 64];
__device__ __align__(16) float g_q[4 * NN * 16];    // head-major
__device__ __align__(16) float g_k[4 * NN * 16];
__device__ __align__(16) float g_v[4 * NN * 16];
__device__ __align__(16) float g_oacc[NN * 64];
__device__ __align__(16) float g_lacc[NN * 4];

#define MMA_TF32(D, A, B0, B1) \
    asm volatile("mma.sync.aligned.m16n8k8.row.col.f32.tf32.tf32.f32 " \
                 "{%0,%1,%2,%3},{%4,%5,%6,%7},{%8,%9},{%0,%1,%2,%3};" \
                 : "+f"((D)[0]), "+f"((D)[1]), "+f"((D)[2]), "+f"((D)[3]) \
                 : "r"((A)[0]), "r"((A)[1]), "r"((A)[2]), "r"((A)[3]), "r"(B0), "r"(B1))

// ===== K1: degree norms + per-type projection + zero accumulators. grid 768, block 256 =====
__global__ __launch_bounds__(256) void k_degproj(const float* __restrict__ graph,
                                                 const float* __restrict__ drug_f,
                                                 const float* __restrict__ dis_f,
                                                 const float* __restrict__ drug_w,
                                                 const float* __restrict__ dis_w) {
    __shared__ float w[4096];
    __shared__ float fr[512];
    __shared__ float nrm[8];
    int tid = threadIdx.x;
    int wid = tid >> 5, lane = tid & 31;
    int row0 = blockIdx.x * 8;
    int row = row0 + wid;
    // row sum -> norm
    const float4* gr = reinterpret_cast<const float4*>(graph + (size_t)row * NN);
    float s = 0.f;
    #pragma unroll 4
    for (int i = lane; i < NN / 4; i += 32) { float4 t = gr[i]; s += (t.x + t.y) + (t.z + t.w); }
    #pragma unroll
    for (int o = 16; o; o >>= 1) s += __shfl_xor_sync(0xffffffffu, s, o);
    if (lane == 0) { float nr = rsqrtf(fmaxf(s, 1.0f)); g_norm[row] = nr; nrm[wid] = nr; }
    // zero accumulators
    int t0 = blockIdx.x * 256 + tid;
    g_target[t0] = 0.f; g_target[t0 + 196608] = 0.f;
    g_oacc[t0] = 0.f;   g_oacc[t0 + 196608] = 0.f;
    if (t0 < NN * 4) g_lacc[t0] = 0.f;
    // stage weights + features (rows never straddle the drug/disease split: 3072 % 8 == 0)
    const float* W = (row0 < NDRUG) ? drug_w : dis_w;
    for (int i = tid; i < 4096; i += 256) w[i] = W[i];
    for (int rep = 0; rep < 2; rep++) {
        int idx = rep * 256 + tid;
        int r = idx >> 6, d = idx & 63;
        int rr = row0 + r;
        fr[idx] = (row0 < NDRUG) ? drug_f[(size_t)rr * 64 + d]
                                 : dis_f[(size_t)(rr - NDRUG) * 64 + d];
    }
    __syncthreads();
    // projection: 8 rows x 64 dims
    for (int rep = 0; rep < 2; rep++) {
        int idx = rep * 256 + tid;
        int r = idx >> 6, d = idx & 63;
        float acc = 0.f;
        #pragma unroll 16
        for (int k = 0; k < 64; k++) acc += fr[r * 64 + k] * w[k * 64 + d];
        g_xn[(size_t)(row0 + r) * 64 + d] = acc * nrm[r];
    }
}

// ===== K2: target += (graph @ xn) * row_norm via tf32 mma. grid (48,3), block 256 =====
#define AST 36
#define BST 72
__global__ __launch_bounds__(256) void k_spmm(const float* __restrict__ graph) {
    __shared__ __align__(16) float As[128 * AST];
    __shared__ __align__(16) float Bs[32 * BST];
    int tid = threadIdx.x;
    int w = tid >> 5, lane = tid & 31, g = lane >> 2, t = lane & 3;
    int rowbase = blockIdx.x * 128;
    int kstart = blockIdx.y * 2048;

    float o[8][4];
    #pragma unroll
    for (int nt = 0; nt < 8; nt++)
        #pragma unroll
        for (int i = 0; i < 4; i++) o[nt][i] = 0.f;

    int ar = tid >> 1, ac = (tid & 1) * 16;
    int br = tid >> 3, bc = (tid & 7) * 8;

    for (int kb = 0; kb < 2048; kb += 32) {
        const float* gp = graph + (size_t)(rowbase + ar) * NN + kstart + kb + ac;
        float4 a0 = *reinterpret_cast<const float4*>(gp);
        float4 a1 = *reinterpret_cast<const float4*>(gp + 4);
        float4 a2 = *reinterpret_cast<const float4*>(gp + 8);
        float4 a3 = *reinterpret_cast<const float4*>(gp + 12);
        const float* bp = g_xn + (size_t)(kstart + kb + br) * 64 + bc;
        float4 b0 = *reinterpret_cast<const float4*>(bp);
        float4 b1 = *reinterpret_cast<const float4*>(bp + 4);
        __syncthreads();
        *reinterpret_cast<float4*>(As + ar * AST + ac)      = a0;
        *reinterpret_cast<float4*>(As + ar * AST + ac + 4)  = a1;
        *reinterpret_cast<float4*>(As + ar * AST + ac + 8)  = a2;
        *reinterpret_cast<float4*>(As + ar * AST + ac + 12) = a3;
        *reinterpret_cast<float4*>(Bs + br * BST + bc)     = b0;
        *reinterpret_cast<float4*>(Bs + br * BST + bc + 4) = b1;
        __syncthreads();
        #pragma unroll
        for (int kc = 0; kc < 4; kc++) {
            unsigned a[4];
            a[0] = __float_as_uint(As[(w * 16 + g) * AST + kc * 8 + t]);
            a[1] = __float_as_uint(As[(w * 16 + g + 8) * AST + kc * 8 + t]);
            a[2] = __float_as_uint(As[(w * 16 + g) * AST + kc * 8 + t + 4]);
            a[3] = __float_as_uint(As[(w * 16 + g + 8) * AST + kc * 8 + t + 4]);
            #pragma unroll
            for (int nt = 0; nt < 8; nt++) {
                unsigned bb0 = __float_as_uint(Bs[(kc * 8 + t) * BST + nt * 8 + g]);
                unsigned bb1 = __float_as_uint(Bs[(kc * 8 + t + 4) * BST + nt * 8 + g]);
                MMA_TF32(o[nt], a, bb0, bb1);
            }
        }
    }
    int r0 = rowbase + w * 16 + g, r1 = r0 + 8;
    float n0 = g_norm[r0], n1 = g_norm[r1];
    #pragma unroll
    for (int nt = 0; nt < 8; nt++) {
        int c = nt * 8 + 2 * t;
        atomicAdd(&g_target[(size_t)r0 * 64 + c],     o[nt][0] * n0);
        atomicAdd(&g_target[(size_t)r0 * 64 + c + 1], o[nt][1] * n0);
        atomicAdd(&g_target[(size_t)r1 * 64 + c],     o[nt][2] * n1);
        atomicAdd(&g_target[(size_t)r1 * 64 + c + 1], o[nt][3] * n1);
    }
}

// ===== K3: time embedding + MLP -> aux. grid 768, block 256, 8 nodes/CTA =====
__global__ __launch_bounds__(256) void k_mlp(const int* __restrict__ tsteps,
                                             const float* __restrict__ emb_w, const float* __restrict__ emb_b,
                                             const float* __restrict__ in_w,  const float* __restrict__ in_b,
                                             const float* __restrict__ out_w, const float* __restrict__ out_b) {
    __shared__ float cs[8 * 81];
    __shared__ float hs[8 * 257];
    int tid = threadIdx.x;
    int base = blockIdx.x * 8;
    for (int idx = tid; idx < 8 * 64; idx += 256) {
        int n = idx >> 6, d = idx & 63;
        cs[n * 81 + d] = g_target[(size_t)(base + n) * 64 + d];
    }
    if (tid < 128) {   // 8 nodes x 16 emb
        int n = tid >> 4, e = tid & 15;
        float t = (float)tsteps[base + n];
        float acc = emb_b[e];
        for (int k = 0; k < 16; k++) {
            int j = k & 7;
            float fr = expf(-1.15129254649702f * (float)j);
            float te = (k < 8) ? cosf(t * fr) : sinf(t * fr);
            acc += te * emb_w[k * 16 + e];
        }
        cs[n * 81 + 64 + e] = acc;
    }
    __syncthreads();
    {   // hidden unit j = tid for 8 nodes
        float acc[8];
        #pragma unroll
        for (int n = 0; n < 8; n++) acc[n] = 0.f;
        #pragma unroll 4
        for (int k = 0; k < 80; k++) {
            float w = in_w[k * 256 + tid];
            #pragma unroll
            for (int n = 0; n < 8; n++) acc[n] += cs[n * 81 + k] * w;
        }
        float bj = in_b[tid];
        #pragma unroll
        for (int n = 0; n < 8; n++) hs[n * 257 + tid] = tanhf(acc[n] + bj);
    }
    __syncthreads();
    {   // output: column d for 2 nodes each
        int d = tid & 63, gg = tid >> 6;
        float oa0 = 0.f, oa1 = 0.f;
        #pragma unroll 4
        for (int k = 0; k < 256; k++) {
            float w = out_w[k * 64 + d];
            oa0 += hs[(gg * 2 + 0) * 257 + k] * w;
            oa1 += hs[(gg * 2 + 1) * 257 + k] * w;
        }
        float bd = out_b[d];
        g_aux[(size_t)(base + gg * 2 + 0) * 64 + d] = oa0 + bd;
        g_aux[(size_t)(base + gg * 2 + 1) * 64 + d] = oa1 + bd;
    }
}

// ===== K4: q/k/v projections (head-major). grid 1536, block 256 =====
__global__ __launch_bounds__(256) void k_qkv(const float* __restrict__ wq, const float* __restrict__ bq,
                                             const float* __restrict__ wk, const float* __restrict__ bk,
                                             const float* __restrict__ wv, const float* __restrict__ bv) {
    __shared__ float w[4096];
    __shared__ float st[256], sa[256];
    int r = threadIdx.x >> 6, d = threadIdx.x & 63;
    int row = blockIdx.x * 4 + r;
    st[r * 64 + d] = g_target[(size_t)row * 64 + d];
    sa[r * 64 + d] = g_aux[(size_t)row * 64 + d];
    int h = d >> 4, hd = d & 15;
    size_t oidx = ((size_t)h * NN + row) * 16 + hd;

    for (int i = threadIdx.x; i < 4096; i += 256) w[i] = wq[i];
    __syncthreads();
    float acc = bq[d];
    #pragma unroll 16
    for (int k = 0; k < 64; k++) acc += st[r * 64 + k] * w[k * 64 + d];
    g_q[oidx] = acc;
    __syncthreads();

    for (int i = threadIdx.x; i < 4096; i += 256) w[i] = wk[i];
    __syncthreads();
    acc = bk[d];
    #pragma unroll 16
    for (int k = 0; k < 64; k++) acc += sa[r * 64 + k] * w[k * 64 + d];
    g_k[oidx] = acc;
    __syncthreads();

    for (int i = threadIdx.x; i < 4096; i += 256) w[i] = wv[i];
    __syncthreads();
    acc = bv[d];
    #pragma unroll 16
    for (int k = 0; k < 64; k++) acc += sa[r * 64 + k] * w[k * 64 + d];
    g_v[oidx] = acc;
}

// ===== K5: attention via tf32 mma. grid (24,4,3), block 256, dyn smem 81152 B =====
#define KS_STR 20
#define VS_STR 25
#define PB_STR 68
__global__ __launch_bounds__(256) void k_attn() {
    extern __shared__ float sm[];
    float* Ks  = sm;            // 64*20 = 1280
    float* Vsb = sm + 1280;     // 64*25 = 1600
    float* Psm = sm + 2880;     // 8*32*68 = 17408
    int tid = threadIdx.x;
    int w = tid >> 5, lane = tid & 31;
    int g = lane >> 2, t = lane & 3;
    int h = blockIdx.y;
    int qn0 = blockIdx.x * 256 + w * 32;
    float* Pb = Psm + w * 32 * PB_STR;

    for (int idx = tid; idx < 64 * 9; idx += 256) {
        int row = idx / 9, c = 16 + idx % 9;
        Vsb[row * VS_STR + c] = (c == 16) ? 1.0f : 0.0f;
    }

    const float* qb = g_q + ((size_t)h * NN + qn0) * 16;
    unsigned aq[2][2][4];
    #pragma unroll
    for (int mt = 0; mt < 2; mt++)
        #pragma unroll
        for (int kc = 0; kc < 2; kc++) {
            aq[mt][kc][0] = __float_as_uint(0.25f * qb[(mt * 16 + g) * 16 + kc * 8 + t]);
            aq[mt][kc][1] = __float_as_uint(0.25f * qb[(mt * 16 + g + 8) * 16 + kc * 8 + t]);
            aq[mt][kc][2] = __float_as_uint(0.25f * qb[(mt * 16 + g) * 16 + kc * 8 + t + 4]);
            aq[mt][kc][3] = __float_as_uint(0.25f * qb[(mt * 16 + g + 8) * 16 + kc * 8 + t + 4]);
        }

    float o[2][3][4];
    #pragma unroll
    for (int mt = 0; mt < 2; mt++)
        #pragma unroll
        for (int nt = 0; nt < 3; nt++)
            #pragma unroll
            for (int i = 0; i < 4; i++) o[mt][nt][i] = 0.f;

    int kbase = blockIdx.z * 2048;
    int krow = tid >> 2, kq = tid & 3;   // 4 threads/key
    for (int c0 = 0; c0 < 2048; c0 += 64) {
        __syncthreads();
        {
            int key = kbase + c0 + krow;
            float4 kv = *reinterpret_cast<const float4*>(g_k + ((size_t)h * NN + key) * 16 + kq * 4);
            float4 vv = *reinterpret_cast<const float4*>(g_v + ((size_t)h * NN + key) * 16 + kq * 4);
            *reinterpret_cast<float4*>(Ks + krow * KS_STR + kq * 4) = kv;
            float* vd = Vsb + krow * VS_STR + kq * 4;
            vd[0] = vv.x; vd[1] = vv.y; vd[2] = vv.z; vd[3] = vv.w;
        }
        __syncthreads();

        float d[2][8][4];
        #pragma unroll
        for (int mt = 0; mt < 2; mt++)
            #pragma unroll
            for (int nt = 0; nt < 8; nt++)
                #pragma unroll
                for (int i = 0; i < 4; i++) d[mt][nt][i] = 0.f;
        #pragma unroll
        for (int kc = 0; kc < 2; kc++)
            #pragma unroll
            for (int nt = 0; nt < 8; nt++) {
                unsigned b0 = __float_as_uint(Ks[(nt * 8 + g) * KS_STR + kc * 8 + t]);
                unsigned b1 = __float_as_uint(Ks[(nt * 8 + g) * KS_STR + kc * 8 + t + 4]);
                MMA_TF32(d[0][nt], aq[0][kc], b0, b1);
                MMA_TF32(d[1][nt], aq[1][kc], b0, b1);
            }

        #pragma unroll
        for (int mt = 0; mt < 2; mt++)
            #pragma unroll
            for (int nt = 0; nt < 8; nt++) {
                float2 p01, p23;
                p01.x = __expf(d[mt][nt][0]); p01.y = __expf(d[mt][nt][1]);
                p23.x = __expf(d[mt][nt][2]); p23.y = __expf(d[mt][nt][3]);
                int col = nt * 8 + 2 * t;
                *reinterpret_cast<float2*>(Pb + (mt * 16 + g) * PB_STR + col) = p01;
                *reinterpret_cast<float2*>(Pb + (mt * 16 + g + 8) * PB_STR + col) = p23;
            }
        __syncwarp();

        #pragma unroll
        for (int kc = 0; kc < 8; kc++) {
            unsigned pa[2][4];
            #pragma unroll
            for (int mt = 0; mt < 2; mt++) {
                pa[mt][0] = __float_as_uint(Pb[(mt * 16 + g) * PB_STR + kc * 8 + t]);
                pa[mt][1] = __float_as_uint(Pb[(mt * 16 + g + 8) * PB_STR + kc * 8 + t]);
                pa[mt][2] = __float_as_uint(Pb[(mt * 16 + g) * PB_STR + kc * 8 + t + 4]);
                pa[mt][3] = __float_as_uint(Pb[(mt * 16 + g + 8) * PB_STR + kc * 8 + t + 4]);
            }
            #pragma unroll
            for (int nt = 0; nt < 3; nt++) {
                unsigned b0 = __float_as_uint(Vsb[(kc * 8 + t) * VS_STR + nt * 8 + g]);
                unsigned b1 = __float_as_uint(Vsb[(kc * 8 + t + 4) * VS_STR + nt * 8 + g]);
                MMA_TF32(o[0][nt], pa[0], b0, b1);
                MMA_TF32(o[1][nt], pa[1], b0, b1);
            }
        }
        __syncwarp();
    }

    #pragma unroll
    for (int mt = 0; mt < 2; mt++) {
        int r0 = qn0 + mt * 16 + g, r1 = r0 + 8;
        #pragma unroll
        for (int nt = 0; nt < 2; nt++) {
            int c = h * 16 + nt * 8 + 2 * t;
            atomicAdd(&g_oacc[(size_t)r0 * 64 + c],     o[mt][nt][0]);
            atomicAdd(&g_oacc[(size_t)r0 * 64 + c + 1], o[mt][nt][1]);
            atomicAdd(&g_oacc[(size_t)r1 * 64 + c],     o[mt][nt][2]);
            atomicAdd(&g_oacc[(size_t)r1 * 64 + c + 1], o[mt][nt][3]);
        }
        if (t == 0) {
            atomicAdd(&g_lacc[r0 * 4 + h], o[mt][2][0]);
            atomicAdd(&g_lacc[r1 * 4 + h], o[mt][2][2]);
        }
    }
}

// ===== K6: wo proj + fuse + residual LN -> out. grid 1536, block 256 =====
__global__ __launch_bounds__(256) void k_final(const float* __restrict__ wo, const float* __restrict__ bo,
                                               const float* __restrict__ fuse_w, const float* __restrict__ fuse_b,
                                               const float* __restrict__ ln_g, const float* __restrict__ ln_b,
                                               float* __restrict__ out) {
    __shared__ float w[4096];
    __shared__ float st[256], sao[256], sy[256];
    int r = threadIdx.x >> 6, d = threadIdx.x & 63;
    int row = blockIdx.x * 4 + r;
    st[r * 64 + d] = g_target[(size_t)row * 64 + d];
    float lh = g_lacc[row * 4 + (d >> 4)];
    sy[r * 64 + d] = g_oacc[(size_t)row * 64 + d] / lh;
    for (int i = threadIdx.x; i < 4096; i += 256) w[i] = wo[i];
    __syncthreads();
    float acc = bo[d];
    #pragma unroll 16
    for (int k = 0; k < 64; k++) acc += sy[r * 64 + k] * w[k * 64 + d];
    __syncthreads();
    sao[r * 64 + d] = acc;
    for (int i = threadIdx.x; i < 4096; i += 256) w[i] = fuse_w[i];
    __syncthreads();
    float f = fuse_b[d];
    #pragma unroll 16
    for (int k = 0; k < 64; k++) f += st[r * 64 + k] * w[k * 64 + d];
    __syncthreads();
    for (int i = threadIdx.x; i < 4096; i += 256) w[i] = fuse_w[4096 + i];
    __syncthreads();
    #pragma unroll 16
    for (int k = 0; k < 64; k++) f += sao[r * 64 + k] * w[k * 64 + d];
    float y = f + st[r * 64 + d];
    __syncthreads();
    sy[r * 64 + d] = y;
    __syncthreads();
    float mu = 0.f;
    #pragma unroll 16
    for (int k = 0; k < 64; k++) mu += sy[r * 64 + k];
    mu *= (1.0f / 64.0f);
    float var = 0.f;
    #pragma unroll 16
    for (int k = 0; k < 64; k++) { float tt = sy[r * 64 + k] - mu; var += tt * tt; }
    var *= (1.0f / 64.0f);
    out[(size_t)row * 64 + d] = (y - mu) * rsqrtf(var + 1e-5f) * ln_g[d] + ln_b[d];
}

extern "C" void kernel_launch(void* const* d_in, const int* in_sizes, int n_in,
                              void* d_out, int out_size) {
    const float* graph     = (const float*)d_in[0];
    const float* drug_f    = (const float*)d_in[1];
    const float* disease_f = (const float*)d_in[2];
    const int*   tsteps    = (const int*)  d_in[3];
    const float* drug_w    = (const float*)d_in[4];
    const float* disease_w = (const float*)d_in[5];
    const float* emb_w     = (const float*)d_in[6];
    const float* emb_b     = (const float*)d_in[7];
    const float* in_w      = (const float*)d_in[8];
    const float* in_b      = (const float*)d_in[9];
    const float* out_w     = (const float*)d_in[10];
    const float* out_b     = (const float*)d_in[11];
    const float* wq = (const float*)d_in[12]; const float* bq = (const float*)d_in[13];
    const float* wk = (const float*)d_in[14]; const float* bk = (const float*)d_in[15];
    const float* wv = (const float*)d_in[16]; const float* bv = (const float*)d_in[17];
    const float* wo = (const float*)d_in[18]; const float* bo = (const float*)d_in[19];
    const float* fuse_w = (const float*)d_in[20]; const float* fuse_b = (const float*)d_in[21];
    const float* ln_g   = (const float*)d_in[22]; const float* ln_b   = (const float*)d_in[23];
    float* out = (float*)d_out;

    static int attr_set = 0;
    if (!attr_set) {
        cudaFuncSetAttribute(k_attn, cudaFuncAttributeMaxDynamicSharedMemorySize, 81152);
        attr_set = 1;
    }

    k_degproj<<<768, 256>>>(graph, drug_f, disease_f, drug_w, disease_w);
    k_spmm   <<<dim3(48, 3), 256>>>(graph);
    k_mlp    <<<768, 256>>>(tsteps, emb_w, emb_b, in_w, in_b, out_w, out_b);
    k_qkv    <<<1536, 256>>>(wq, bq, wk, bk, wv, bv);
    k_attn   <<<dim3(24, 4, 3), 256, 81152>>>();
    k_final  <<<1536, 256>>>(wo, bo, fuse_w, fuse_b, ln_g, ln_b, out);
}

// round 11
// speedup vs baseline: 2.2816x; 1.0501x over previous
#include <cuda_runtime.h>
#include <math.h>

#define NN 6144
#define NDRUG 3072

// ---------- scratch (device globals; no allocation allowed) ----------
__device__ __align__(16) float g_norm[NN];
__device__ __align__(16) float g_xn[NN * 64];
__device__ __align__(16) float g_target[NN * 64];
__device__ __align__(16) float g_aux[NN * 64];
__device__ __align__(16) float g_q[4 * NN * 16];    // head-major
__device__ __align__(16) float g_k[4 * NN * 16];
__device__ __align__(16) float g_v[4 * NN * 16];
__device__ __align__(16) float g_oacc[NN * 64];
__device__ __align__(16) float g_lacc[NN * 4];

#define MMA_TF32(D, A, B0, B1) \
    asm volatile("mma.sync.aligned.m16n8k8.row.col.f32.tf32.tf32.f32 " \
                 "{%0,%1,%2,%3},{%4,%5,%6,%7},{%8,%9},{%0,%1,%2,%3};" \
                 : "+f"((D)[0]), "+f"((D)[1]), "+f"((D)[2]), "+f"((D)[3]) \
                 : "r"((A)[0]), "r"((A)[1]), "r"((A)[2]), "r"((A)[3]), "r"(B0), "r"(B1))

// ===== K1: degree norms + per-type projection + zero accumulators. grid 768, block 256 =====
__global__ __launch_bounds__(256) void k_degproj(const float* __restrict__ graph,
                                                 const float* __restrict__ drug_f,
                                                 const float* __restrict__ dis_f,
                                                 const float* __restrict__ drug_w,
                                                 const float* __restrict__ dis_w) {
    __shared__ float w[4096];
    __shared__ float fr[512];
    __shared__ float nrm[8];
    int tid = threadIdx.x;
    int wid = tid >> 5, lane = tid & 31;
    int row0 = blockIdx.x * 8;
    int row = row0 + wid;
    const float4* gr = reinterpret_cast<const float4*>(graph + (size_t)row * NN);
    float s = 0.f;
    #pragma unroll 4
    for (int i = lane; i < NN / 4; i += 32) { float4 t = gr[i]; s += (t.x + t.y) + (t.z + t.w); }
    #pragma unroll
    for (int o = 16; o; o >>= 1) s += __shfl_xor_sync(0xffffffffu, s, o);
    if (lane == 0) { float nr = rsqrtf(fmaxf(s, 1.0f)); g_norm[row] = nr; nrm[wid] = nr; }
    int t0 = blockIdx.x * 256 + tid;
    g_target[t0] = 0.f; g_target[t0 + 196608] = 0.f;
    g_oacc[t0] = 0.f;   g_oacc[t0 + 196608] = 0.f;
    if (t0 < NN * 4) g_lacc[t0] = 0.f;
    const float* W = (row0 < NDRUG) ? drug_w : dis_w;
    for (int i = tid; i < 4096; i += 256) w[i] = W[i];
    for (int rep = 0; rep < 2; rep++) {
        int idx = rep * 256 + tid;
        int r = idx >> 6, d = idx & 63;
        int rr = row0 + r;
        fr[idx] = (row0 < NDRUG) ? drug_f[(size_t)rr * 64 + d]
                                 : dis_f[(size_t)(rr - NDRUG) * 64 + d];
    }
    __syncthreads();
    for (int rep = 0; rep < 2; rep++) {
        int idx = rep * 256 + tid;
        int r = idx >> 6, d = idx & 63;
        float acc = 0.f;
        #pragma unroll 16
        for (int k = 0; k < 64; k++) acc += fr[r * 64 + k] * w[k * 64 + d];
        g_xn[(size_t)(row0 + r) * 64 + d] = acc * nrm[r];
    }
}

// ===== K2: target += (graph @ xn) * row_norm via tf32 mma. grid (48,3), block 256 =====
#define AST 36
#define BST 72
__global__ __launch_bounds__(256) void k_spmm(const float* __restrict__ graph) {
    __shared__ __align__(16) float As[128 * AST];
    __shared__ __align__(16) float Bs[32 * BST];
    int tid = threadIdx.x;
    int w = tid >> 5, lane = tid & 31, g = lane >> 2, t = lane & 3;
    int rowbase = blockIdx.x * 128;
    int kstart = blockIdx.y * 2048;

    float o[8][4];
    #pragma unroll
    for (int nt = 0; nt < 8; nt++)
        #pragma unroll
        for (int i = 0; i < 4; i++) o[nt][i] = 0.f;

    int ar = tid >> 1, ac = (tid & 1) * 16;
    int br = tid >> 3, bc = (tid & 7) * 8;

    for (int kb = 0; kb < 2048; kb += 32) {
        const float* gp = graph + (size_t)(rowbase + ar) * NN + kstart + kb + ac;
        float4 a0 = *reinterpret_cast<const float4*>(gp);
        float4 a1 = *reinterpret_cast<const float4*>(gp + 4);
        float4 a2 = *reinterpret_cast<const float4*>(gp + 8);
        float4 a3 = *reinterpret_cast<const float4*>(gp + 12);
        const float* bp = g_xn + (size_t)(kstart + kb + br) * 64 + bc;
        float4 b0 = *reinterpret_cast<const float4*>(bp);
        float4 b1 = *reinterpret_cast<const float4*>(bp + 4);
        __syncthreads();
        *reinterpret_cast<float4*>(As + ar * AST + ac)      = a0;
        *reinterpret_cast<float4*>(As + ar * AST + ac + 4)  = a1;
        *reinterpret_cast<float4*>(As + ar * AST + ac + 8)  = a2;
        *reinterpret_cast<float4*>(As + ar * AST + ac + 12) = a3;
        *reinterpret_cast<float4*>(Bs + br * BST + bc)     = b0;
        *reinterpret_cast<float4*>(Bs + br * BST + bc + 4) = b1;
        __syncthreads();
        #pragma unroll
        for (int kc = 0; kc < 4; kc++) {
            unsigned a[4];
            a[0] = __float_as_uint(As[(w * 16 + g) * AST + kc * 8 + t]);
            a[1] = __float_as_uint(As[(w * 16 + g + 8) * AST + kc * 8 + t]);
            a[2] = __float_as_uint(As[(w * 16 + g) * AST + kc * 8 + t + 4]);
            a[3] = __float_as_uint(As[(w * 16 + g + 8) * AST + kc * 8 + t + 4]);
            #pragma unroll
            for (int nt = 0; nt < 8; nt++) {
                unsigned bb0 = __float_as_uint(Bs[(kc * 8 + t) * BST + nt * 8 + g]);
                unsigned bb1 = __float_as_uint(Bs[(kc * 8 + t + 4) * BST + nt * 8 + g]);
                MMA_TF32(o[nt], a, bb0, bb1);
            }
        }
    }
    int r0 = rowbase + w * 16 + g, r1 = r0 + 8;
    float n0 = g_norm[r0], n1 = g_norm[r1];
    #pragma unroll
    for (int nt = 0; nt < 8; nt++) {
        int c = nt * 8 + 2 * t;
        atomicAdd(&g_target[(size_t)r0 * 64 + c],     o[nt][0] * n0);
        atomicAdd(&g_target[(size_t)r0 * 64 + c + 1], o[nt][1] * n0);
        atomicAdd(&g_target[(size_t)r1 * 64 + c],     o[nt][2] * n1);
        atomicAdd(&g_target[(size_t)r1 * 64 + c + 1], o[nt][3] * n1);
    }
}

// ===== K3: time embedding + MLP -> aux. grid 768, block 256, 8 nodes/CTA =====
__global__ __launch_bounds__(256) void k_mlp(const int* __restrict__ tsteps,
                                             const float* __restrict__ emb_w, const float* __restrict__ emb_b,
                                             const float* __restrict__ in_w,  const float* __restrict__ in_b,
                                             const float* __restrict__ out_w, const float* __restrict__ out_b) {
    __shared__ float cs[8 * 81];
    __shared__ float hs[8 * 257];
    int tid = threadIdx.x;
    int base = blockIdx.x * 8;
    for (int idx = tid; idx < 8 * 64; idx += 256) {
        int n = idx >> 6, d = idx & 63;
        cs[n * 81 + d] = g_target[(size_t)(base + n) * 64 + d];
    }
    if (tid < 128) {
        int n = tid >> 4, e = tid & 15;
        float t = (float)tsteps[base + n];
        float acc = emb_b[e];
        for (int k = 0; k < 16; k++) {
            int j = k & 7;
            float fr = expf(-1.15129254649702f * (float)j);
            float te = (k < 8) ? cosf(t * fr) : sinf(t * fr);
            acc += te * emb_w[k * 16 + e];
        }
        cs[n * 81 + 64 + e] = acc;
    }
    __syncthreads();
    {
        float acc[8];
        #pragma unroll
        for (int n = 0; n < 8; n++) acc[n] = 0.f;
        #pragma unroll 4
        for (int k = 0; k < 80; k++) {
            float w = in_w[k * 256 + tid];
            #pragma unroll
            for (int n = 0; n < 8; n++) acc[n] += cs[n * 81 + k] * w;
        }
        float bj = in_b[tid];
        #pragma unroll
        for (int n = 0; n < 8; n++) hs[n * 257 + tid] = tanhf(acc[n] + bj);
    }
    __syncthreads();
    {
        int d = tid & 63, gg = tid >> 6;
        float oa0 = 0.f, oa1 = 0.f;
        #pragma unroll 4
        for (int k = 0; k < 256; k++) {
            float w = out_w[k * 64 + d];
            oa0 += hs[(gg * 2 + 0) * 257 + k] * w;
            oa1 += hs[(gg * 2 + 1) * 257 + k] * w;
        }
        float bd = out_b[d];
        g_aux[(size_t)(base + gg * 2 + 0) * 64 + d] = oa0 + bd;
        g_aux[(size_t)(base + gg * 2 + 1) * 64 + d] = oa1 + bd;
    }
}

// ===== K4: fused q/k/v projections via tf32 mma. grid 48, block 256, dyn smem 121856 B =====
#define QST 68
__global__ __launch_bounds__(256) void k_qkv(const float* __restrict__ wq, const float* __restrict__ bq,
                                             const float* __restrict__ wk, const float* __restrict__ bk,
                                             const float* __restrict__ wv, const float* __restrict__ bv) {
    extern __shared__ float qs[];
    float* At = qs;                   // 128*68
    float* Aa = qs + 128 * QST;       // 128*68
    float* Ws = qs + 256 * QST;       // 192*68 (transposed weights: Ws[n][k])
    __shared__ float bias[192];
    int tid = threadIdx.x;
    int w = tid >> 5, lane = tid & 31, g = lane >> 2, t = lane & 3;
    int row0 = blockIdx.x * 128;

    // stage A matrices (128 rows x 64)
    for (int i = tid; i < 128 * 16; i += 256) {
        int r = i >> 4, c4 = (i & 15) * 4;
        float4 tv = *reinterpret_cast<const float4*>(g_target + (size_t)(row0 + r) * 64 + c4);
        float4 av = *reinterpret_cast<const float4*>(g_aux + (size_t)(row0 + r) * 64 + c4);
        float* td = At + r * QST + c4;
        td[0] = tv.x; td[1] = tv.y; td[2] = tv.z; td[3] = tv.w;
        float* ad = Aa + r * QST + c4;
        ad[0] = av.x; ad[1] = av.y; ad[2] = av.z; ad[3] = av.w;
    }
    // stage transposed weights
    for (int i = tid; i < 4096; i += 256) {
        int k = i >> 6, d = i & 63;
        Ws[d * QST + k]         = wq[i];
        Ws[(64 + d) * QST + k]  = wk[i];
        Ws[(128 + d) * QST + k] = wv[i];
    }
    if (tid < 192) bias[tid] = (tid < 64) ? bq[tid] : (tid < 128) ? bk[tid - 64] : bv[tid - 128];
    __syncthreads();

    float acc[24][4];
    #pragma unroll
    for (int nt = 0; nt < 24; nt++)
        #pragma unroll
        for (int i = 0; i < 4; i++) acc[nt][i] = 0.f;

    #pragma unroll
    for (int kc = 0; kc < 8; kc++) {
        unsigned at[4], aa[4];
        at[0] = __float_as_uint(At[(w * 16 + g) * QST + kc * 8 + t]);
        at[1] = __float_as_uint(At[(w * 16 + g + 8) * QST + kc * 8 + t]);
        at[2] = __float_as_uint(At[(w * 16 + g) * QST + kc * 8 + t + 4]);
        at[3] = __float_as_uint(At[(w * 16 + g + 8) * QST + kc * 8 + t + 4]);
        aa[0] = __float_as_uint(Aa[(w * 16 + g) * QST + kc * 8 + t]);
        aa[1] = __float_as_uint(Aa[(w * 16 + g + 8) * QST + kc * 8 + t]);
        aa[2] = __float_as_uint(Aa[(w * 16 + g) * QST + kc * 8 + t + 4]);
        aa[3] = __float_as_uint(Aa[(w * 16 + g + 8) * QST + kc * 8 + t + 4]);
        #pragma unroll
        for (int nt = 0; nt < 24; nt++) {
            unsigned b0 = __float_as_uint(Ws[(nt * 8 + g) * QST + kc * 8 + t]);
            unsigned b1 = __float_as_uint(Ws[(nt * 8 + g) * QST + kc * 8 + t + 4]);
            MMA_TF32(acc[nt], (nt < 8) ? at : aa, b0, b1);
        }
    }

    int r0 = row0 + w * 16 + g, r1 = r0 + 8;
    #pragma unroll
    for (int nt = 0; nt < 24; nt++) {
        int jj = nt * 8 + 2 * t;
        int sel = jj >> 6, jl = jj & 63;
        float* D = (sel == 0) ? g_q : (sel == 1) ? g_k : g_v;
        int h = jl >> 4, hd = jl & 15;
        int h2 = (jl + 1) >> 4, hd2 = (jl + 1) & 15;
        float b0 = bias[jj], b1 = bias[jj + 1];
        D[((size_t)h * NN + r0) * 16 + hd]   = acc[nt][0] + b0;
        D[((size_t)h2 * NN + r0) * 16 + hd2] = acc[nt][1] + b1;
        D[((size_t)h * NN + r1) * 16 + hd]   = acc[nt][2] + b0;
        D[((size_t)h2 * NN + r1) * 16 + hd2] = acc[nt][3] + b1;
    }
}

// ===== K5: attention via tf32 mma. grid (24,4,3), block 256, dyn smem 81152 B =====
#define KS_STR 20
#define VS_STR 25
#define PB_STR 68
__global__ __launch_bounds__(256) void k_attn() {
    extern __shared__ float sm[];
    float* Ks  = sm;
    float* Vsb = sm + 1280;
    float* Psm = sm + 2880;
    int tid = threadIdx.x;
    int w = tid >> 5, lane = tid & 31;
    int g = lane >> 2, t = lane & 3;
    int h = blockIdx.y;
    int qn0 = blockIdx.x * 256 + w * 32;
    float* Pb = Psm + w * 32 * PB_STR;

    for (int idx = tid; idx < 64 * 9; idx += 256) {
        int row = idx / 9, c = 16 + idx % 9;
        Vsb[row * VS_STR + c] = (c == 16) ? 1.0f : 0.0f;
    }

    const float* qb = g_q + ((size_t)h * NN + qn0) * 16;
    unsigned aq[2][2][4];
    #pragma unroll
    for (int mt = 0; mt < 2; mt++)
        #pragma unroll
        for (int kc = 0; kc < 2; kc++) {
            aq[mt][kc][0] = __float_as_uint(0.25f * qb[(mt * 16 + g) * 16 + kc * 8 + t]);
            aq[mt][kc][1] = __float_as_uint(0.25f * qb[(mt * 16 + g + 8) * 16 + kc * 8 + t]);
            aq[mt][kc][2] = __float_as_uint(0.25f * qb[(mt * 16 + g) * 16 + kc * 8 + t + 4]);
            aq[mt][kc][3] = __float_as_uint(0.25f * qb[(mt * 16 + g + 8) * 16 + kc * 8 + t + 4]);
        }

    float o[2][3][4];
    #pragma unroll
    for (int mt = 0; mt < 2; mt++)
        #pragma unroll
        for (int nt = 0; nt < 3; nt++)
            #pragma unroll
            for (int i = 0; i < 4; i++) o[mt][nt][i] = 0.f;

    int kbase = blockIdx.z * 2048;
    int krow = tid >> 2, kq = tid & 3;
    for (int c0 = 0; c0 < 2048; c0 += 64) {
        __syncthreads();
        {
            int key = kbase + c0 + krow;
            float4 kv = *reinterpret_cast<const float4*>(g_k + ((size_t)h * NN + key) * 16 + kq * 4);
            float4 vv = *reinterpret_cast<const float4*>(g_v + ((size_t)h * NN + key) * 16 + kq * 4);
            *reinterpret_cast<float4*>(Ks + krow * KS_STR + kq * 4) = kv;
            float* vd = Vsb + krow * VS_STR + kq * 4;
            vd[0] = vv.x; vd[1] = vv.y; vd[2] = vv.z; vd[3] = vv.w;
        }
        __syncthreads();

        float d[2][8][4];
        #pragma unroll
        for (int mt = 0; mt < 2; mt++)
            #pragma unroll
            for (int nt = 0; nt < 8; nt++)
                #pragma unroll
                for (int i = 0; i < 4; i++) d[mt][nt][i] = 0.f;
        #pragma unroll
        for (int kc = 0; kc < 2; kc++)
            #pragma unroll
            for (int nt = 0; nt < 8; nt++) {
                unsigned b0 = __float_as_uint(Ks[(nt * 8 + g) * KS_STR + kc * 8 + t]);
                unsigned b1 = __float_as_uint(Ks[(nt * 8 + g) * KS_STR + kc * 8 + t + 4]);
                MMA_TF32(d[0][nt], aq[0][kc], b0, b1);
                MMA_TF32(d[1][nt], aq[1][kc], b0, b1);
            }

        #pragma unroll
        for (int mt = 0; mt < 2; mt++)
            #pragma unroll
            for (int nt = 0; nt < 8; nt++) {
                float2 p01, p23;
                p01.x = __expf(d[mt][nt][0]); p01.y = __expf(d[mt][nt][1]);
                p23.x = __expf(d[mt][nt][2]); p23.y = __expf(d[mt][nt][3]);
                int col = nt * 8 + 2 * t;
                *reinterpret_cast<float2*>(Pb + (mt * 16 + g) * PB_STR + col) = p01;
                *reinterpret_cast<float2*>(Pb + (mt * 16 + g + 8) * PB_STR + col) = p23;
            }
        __syncwarp();

        #pragma unroll
        for (int kc = 0; kc < 8; kc++) {
            unsigned pa[2][4];
            #pragma unroll
            for (int mt = 0; mt < 2; mt++) {
                pa[mt][0] = __float_as_uint(Pb[(mt * 16 + g) * PB_STR + kc * 8 + t]);
                pa[mt][1] = __float_as_uint(Pb[(mt * 16 + g + 8) * PB_STR + kc * 8 + t]);
                pa[mt][2] = __float_as_uint(Pb[(mt * 16 + g) * PB_STR + kc * 8 + t + 4]);
                pa[mt][3] = __float_as_uint(Pb[(mt * 16 + g + 8) * PB_STR + kc * 8 + t + 4]);
            }
            #pragma unroll
            for (int nt = 0; nt < 3; nt++) {
                unsigned b0 = __float_as_uint(Vsb[(kc * 8 + t) * VS_STR + nt * 8 + g]);
                unsigned b1 = __float_as_uint(Vsb[(kc * 8 + t + 4) * VS_STR + nt * 8 + g]);
                MMA_TF32(o[0][nt], pa[0], b0, b1);
                MMA_TF32(o[1][nt], pa[1], b0, b1);
            }
        }
        __syncwarp();
    }

    #pragma unroll
    for (int mt = 0; mt < 2; mt++) {
        int r0 = qn0 + mt * 16 + g, r1 = r0 + 8;
        #pragma unroll
        for (int nt = 0; nt < 2; nt++) {
            int c = h * 16 + nt * 8 + 2 * t;
            atomicAdd(&g_oacc[(size_t)r0 * 64 + c],     o[mt][nt][0]);
            atomicAdd(&g_oacc[(size_t)r0 * 64 + c + 1], o[mt][nt][1]);
            atomicAdd(&g_oacc[(size_t)r1 * 64 + c],     o[mt][nt][2]);
            atomicAdd(&g_oacc[(size_t)r1 * 64 + c + 1], o[mt][nt][3]);
        }
        if (t == 0) {
            atomicAdd(&g_lacc[r0 * 4 + h], o[mt][2][0]);
            atomicAdd(&g_lacc[r1 * 4 + h], o[mt][2][2]);
        }
    }
}

// ===== K6: wo proj + fuse + residual LN -> out. grid 1536, block 256 =====
__global__ __launch_bounds__(256) void k_final(const float* __restrict__ wo, const float* __restrict__ bo,
                                               const float* __restrict__ fuse_w, const float* __restrict__ fuse_b,
                                               const float* __restrict__ ln_g, const float* __restrict__ ln_b,
                                               float* __restrict__ out) {
    __shared__ float w[4096];
    __shared__ float st[256], sao[256], sy[256];
    int r = threadIdx.x >> 6, d = threadIdx.x & 63;
    int row = blockIdx.x * 4 + r;
    st[r * 64 + d] = g_target[(size_t)row * 64 + d];
    float lh = g_lacc[row * 4 + (d >> 4)];
    sy[r * 64 + d] = g_oacc[(size_t)row * 64 + d] / lh;
    for (int i = threadIdx.x; i < 4096; i += 256) w[i] = wo[i];
    __syncthreads();
    float acc = bo[d];
    #pragma unroll 16
    for (int k = 0; k < 64; k++) acc += sy[r * 64 + k] * w[k * 64 + d];
    __syncthreads();
    sao[r * 64 + d] = acc;
    for (int i = threadIdx.x; i < 4096; i += 256) w[i] = fuse_w[i];
    __syncthreads();
    float f = fuse_b[d];
    #pragma unroll 16
    for (int k = 0; k < 64; k++) f += st[r * 64 + k] * w[k * 64 + d];
    __syncthreads();
    for (int i = threadIdx.x; i < 4096; i += 256) w[i] = fuse_w[4096 + i];
    __syncthreads();
    #pragma unroll 16
    for (int k = 0; k < 64; k++) f += sao[r * 64 + k] * w[k * 64 + d];
    float y = f + st[r * 64 + d];
    __syncthreads();
    sy[r * 64 + d] = y;
    __syncthreads();
    float mu = 0.f;
    #pragma unroll 16
    for (int k = 0; k < 64; k++) mu += sy[r * 64 + k];
    mu *= (1.0f / 64.0f);
    float var = 0.f;
    #pragma unroll 16
    for (int k = 0; k < 64; k++) { float tt = sy[r * 64 + k] - mu; var += tt * tt; }
    var *= (1.0f / 64.0f);
    out[(size_t)row * 64 + d] = (y - mu) * rsqrtf(var + 1e-5f) * ln_g[d] + ln_b[d];
}

extern "C" void kernel_launch(void* const* d_in, const int* in_sizes, int n_in,
                              void* d_out, int out_size) {
    const float* graph     = (const float*)d_in[0];
    const float* drug_f    = (const float*)d_in[1];
    const float* disease_f = (const float*)d_in[2];
    const int*   tsteps    = (const int*)  d_in[3];
    const float* drug_w    = (const float*)d_in[4];
    const float* disease_w = (const float*)d_in[5];
    const float* emb_w     = (const float*)d_in[6];
    const float* emb_b     = (const float*)d_in[7];
    const float* in_w      = (const float*)d_in[8];
    const float* in_b      = (const float*)d_in[9];
    const float* out_w     = (const float*)d_in[10];
    const float* out_b     = (const float*)d_in[11];
    const float* wq = (const float*)d_in[12]; const float* bq = (const float*)d_in[13];
    const float* wk = (const float*)d_in[14]; const float* bk = (const float*)d_in[15];
    const float* wv = (const float*)d_in[16]; const float* bv = (const float*)d_in[17];
    const float* wo = (const float*)d_in[18]; const float* bo = (const float*)d_in[19];
    const float* fuse_w = (const float*)d_in[20]; const float* fuse_b = (const float*)d_in[21];
    const float* ln_g   = (const float*)d_in[22]; const float* ln_b   = (const float*)d_in[23];
    float* out = (float*)d_out;

    static int attr_set = 0;
    if (!attr_set) {
        cudaFuncSetAttribute(k_attn, cudaFuncAttributeMaxDynamicSharedMemorySize, 81152);
        cudaFuncSetAttribute(k_qkv,  cudaFuncAttributeMaxDynamicSharedMemorySize, 121856);
        attr_set = 1;
    }

    k_degproj<<<768, 256>>>(graph, drug_f, disease_f, drug_w, disease_w);
    k_spmm   <<<dim3(48, 3), 256>>>(graph);
    k_mlp    <<<768, 256>>>(tsteps, emb_w, emb_b, in_w, in_b, out_w, out_b);
    k_qkv    <<<48, 256, 121856>>>(wq, bq, wk, bk, wv, bv);
    k_attn   <<<dim3(24, 4, 3), 256, 81152>>>();
    k_final  <<<1536, 256>>>(wo, bo, fuse_w, fuse_b, ln_g, ln_b, out);
}